// round 14
// baseline (speedup 1.0000x reference)
#include <cuda_runtime.h>
#include <cuda_bf16.h>
#include <math.h>
#include <stdint.h>

// Problem constants
#define BB   16
#define SS   512
#define INF_ 32
#define DD   768
#define HH   12
#define LL   6
#define DHD  64
#define DFF_ 3072
#define MROWS (BB*SS)   // 8192

// -------------------- device scratch --------------------
__device__ float g_h [MROWS*DD];
__device__ float g_o [MROWS*DD];

__device__ uint32_t g_xs_hi[MROWS*INF_/2],  g_xs_lo[MROWS*INF_/2];
__device__ uint32_t g_hs_hi[MROWS*DD/2],    g_hs_lo[MROWS*DD/2];
__device__ uint32_t g_ff_hi[MROWS*DFF_/2],  g_ff_lo[MROWS*DFF_/2];
__device__ uint32_t g_qkv_hi[MROWS*3*DD/2], g_qkv_lo[MROWS*3*DD/2];
__device__ float    g_qkvb[LL*3*DD];

// split + transposed weights ([N][K/2] words per tensor)
#define W_INW 0
#define W_QKV 12288                       // L x [2304][384], layer stride 884736
#define W_W1  5320704                     // L x [3072][384], layer stride 1179648
#define W_W2  12398592                    // L x [768][1536], layer stride 1179648
#define W_TOT 19476480
__device__ uint32_t g_w_hi[W_TOT];
__device__ uint32_t g_w_lo[W_TOT];

// -------------------- helpers --------------------
__device__ __forceinline__ uint32_t pack_bf16(float x, float y) {
    __nv_bfloat162 t = __floats2bfloat162_rn(x, y);
    return *reinterpret_cast<uint32_t*>(&t);
}

__device__ __forceinline__ float blockReduceSum(float val) {
    __shared__ float sh[8];
    __syncthreads();
    int lane = threadIdx.x & 31, warp = threadIdx.x >> 5;
    int nw = blockDim.x >> 5;
    #pragma unroll
    for (int o = 16; o; o >>= 1) val += __shfl_xor_sync(0xffffffffu, val, o);
    if (lane == 0) sh[warp] = val;
    __syncthreads();
    if (warp == 0) {
        float v = (lane < nw) ? sh[lane] : 0.f;
        #pragma unroll
        for (int o = 4; o; o >>= 1) v += __shfl_xor_sync(0xffffffffu, v, o);
        if (lane == 0) sh[0] = v;
    }
    __syncthreads();
    return sh[0];
}

// fused 2-value block reduce (single barrier round); call once per kernel
__device__ __forceinline__ void blockReduceSum2(float& a, float& b) {
    __shared__ float sh[16];
    int lane = threadIdx.x & 31, warp = threadIdx.x >> 5;
    int nw = blockDim.x >> 5;
    #pragma unroll
    for (int o = 16; o; o >>= 1) {
        a += __shfl_xor_sync(0xffffffffu, a, o);
        b += __shfl_xor_sync(0xffffffffu, b, o);
    }
    if (lane == 0) { sh[warp] = a; sh[warp + 8] = b; }
    __syncthreads();
    if (warp == 0) {
        float va = (lane < nw) ? sh[lane] : 0.f;
        float vb = (lane < nw) ? sh[lane + 8] : 0.f;
        #pragma unroll
        for (int o = 4; o; o >>= 1) {
            va += __shfl_xor_sync(0xffffffffu, va, o);
            vb += __shfl_xor_sync(0xffffffffu, vb, o);
        }
        if (lane == 0) { sh[0] = va; sh[8] = vb; }
    }
    __syncthreads();
    a = sh[0]; b = sh[8];
}

__device__ __forceinline__ void mma16816(float* d, const uint32_t* a, const uint32_t* b) {
    asm volatile(
        "mma.sync.aligned.m16n8k16.row.col.f32.bf16.bf16.f32 "
        "{%0,%1,%2,%3}, {%4,%5,%6,%7}, {%8,%9}, {%0,%1,%2,%3};\n"
        : "+f"(d[0]), "+f"(d[1]), "+f"(d[2]), "+f"(d[3])
        : "r"(a[0]), "r"(a[1]), "r"(a[2]), "r"(a[3]), "r"(b[0]), "r"(b[1]));
}

__device__ __forceinline__ void ldsm4(uint32_t* r, uint32_t addr) {
    asm volatile("ldmatrix.sync.aligned.m8n8.x4.shared.b16 {%0,%1,%2,%3}, [%4];"
                 : "=r"(r[0]), "=r"(r[1]), "=r"(r[2]), "=r"(r[3]) : "r"(addr));
}
__device__ __forceinline__ void ldsm2(uint32_t* r, uint32_t addr) {
    asm volatile("ldmatrix.sync.aligned.m8n8.x2.shared.b16 {%0,%1}, [%2];"
                 : "=r"(r[0]), "=r"(r[1]) : "r"(addr));
}
__device__ __forceinline__ void ldsm2t(uint32_t* r, uint32_t addr) {
    asm volatile("ldmatrix.sync.aligned.m8n8.x2.trans.shared.b16 {%0,%1}, [%2];"
                 : "=r"(r[0]), "=r"(r[1]) : "r"(addr));
}

__device__ __forceinline__ void cp16(uint32_t dst, const void* src) {
    asm volatile("cp.async.cg.shared.global [%0], [%1], 16;\n" :: "r"(dst), "l"(src));
}
__device__ __forceinline__ void cp_commit() { asm volatile("cp.async.commit_group;\n"); }
__device__ __forceinline__ void cp_wait0()  { asm volatile("cp.async.wait_group 0;\n"); }
__device__ __forceinline__ void cp_wait1()  { asm volatile("cp.async.wait_group 1;\n"); }

__device__ __forceinline__ uint32_t smem_u32(const void* p) {
    return (uint32_t)__cvta_generic_to_shared(p);
}

// -------------------- weight transpose + split (vectorized) -----------------
__device__ __forceinline__ void wsplit_body(
    const float* __restrict__ W, uint32_t* __restrict__ hi,
    uint32_t* __restrict__ lo, int K, int N, int n0, int k0, int tid,
    float (*t)[65])
{
    #pragma unroll
    for (int i = 0; i < 4; i++) {
        int idx = tid + i * 256;
        int k = idx >> 4, f = (idx & 15) * 4;
        if (k0 + k < K) {
            float4 v = *(const float4*)(W + (size_t)(k0 + k) * N + n0 + f);
            t[k][f] = v.x; t[k][f + 1] = v.y; t[k][f + 2] = v.z; t[k][f + 3] = v.w;
        }
    }
    __syncthreads();
    const int Kw = K >> 1;
    #pragma unroll
    for (int i = 0; i < 2; i++) {
        int idx = tid + i * 256;
        int n = idx >> 3, wq = idx & 7;
        if (k0 / 2 + wq * 4 < Kw) {
            uint32_t hh[4], ll[4];
            #pragma unroll
            for (int j = 0; j < 4; j++) {
                int kk = wq * 8 + j * 2;
                float a = t[kk][n], b = t[kk + 1][n];
                float ha = __bfloat162float(__float2bfloat16_rn(a));
                float hb = __bfloat162float(__float2bfloat16_rn(b));
                hh[j] = pack_bf16(ha, hb);
                ll[j] = pack_bf16(a - ha, b - hb);
            }
            size_t wi = (size_t)(n0 + n) * Kw + k0 / 2 + wq * 4;
            *(uint4*)(hi + wi) = make_uint4(hh[0], hh[1], hh[2], hh[3]);
            *(uint4*)(lo + wi) = make_uint4(ll[0], ll[1], ll[2], ll[3]);
        }
    }
}

__global__ __launch_bounds__(256)
void wsplit(const float* __restrict__ W, uint32_t* __restrict__ hi,
            uint32_t* __restrict__ lo, int K, int N, long lstr)
{
    __shared__ float t[64][65];
    const int l = blockIdx.z;
    wsplit_body(W + (size_t)l * K * N, hi + (size_t)l * lstr,
                lo + (size_t)l * lstr, K, N,
                blockIdx.x * 64, blockIdx.y * 64, threadIdx.x, t);
}

__global__ __launch_bounds__(256)
void wsplit3(const float* __restrict__ q, const float* __restrict__ k,
             const float* __restrict__ v, uint32_t* __restrict__ hi,
             uint32_t* __restrict__ lo)
{
    __shared__ float t[64][65];
    const int z = blockIdx.z, l = z / 3, t3 = z % 3;
    const float* W = (t3 == 0 ? q : (t3 == 1 ? k : v)) + (size_t)l * DD * DD;
    const size_t off = (size_t)l * (3L * DD * DD / 2) + (size_t)t3 * (DD * DD / 2);
    wsplit_body(W, hi + off, lo + off, DD, DD,
                blockIdx.x * 64, blockIdx.y * 64, threadIdx.x, t);
}

__global__ void xsplit(const float* __restrict__ src, uint32_t* __restrict__ hi,
                       uint32_t* __restrict__ lo, int nPairs)
{
    int i = blockIdx.x * blockDim.x + threadIdx.x;
    if (i < nPairs) {
        float2 v = *(const float2*)(src + 2 * i);
        float h0 = __bfloat162float(__float2bfloat16_rn(v.x));
        float h1 = __bfloat162float(__float2bfloat16_rn(v.y));
        hi[i] = pack_bf16(h0, h1);
        lo[i] = pack_bf16(v.x - h0, v.y - h1);
    }
}

__global__ void catb(const float* __restrict__ qb, const float* __restrict__ kb,
                     const float* __restrict__ vb, float* __restrict__ o)
{
    int idx = blockIdx.x * 256 + threadIdx.x;
    if (idx < LL * 3 * DD) {
        int l = idx / (3 * DD), r = idx % (3 * DD);
        float v = (r < DD) ? qb[l * DD + r]
                : (r < 2 * DD) ? kb[l * DD + r - DD] : vb[l * DD + r - 2 * DD];
        o[idx] = v;
    }
}

// -------------------- legacy bf16x2 GEMM (K=32 in-proj only) ----------------
#define RS 20
#define STG 10240
#define GEMM_SMEM (2 * STG * 4)

__global__ __launch_bounds__(256)
void gemm_tc(const uint32_t* __restrict__ A_hi, const uint32_t* __restrict__ A_lo,
             const uint32_t* __restrict__ W_hi, const uint32_t* __restrict__ W_lo,
             const float* __restrict__ bias, const float* __restrict__ pos,
             float* __restrict__ C, uint32_t* __restrict__ Cs_hi,
             uint32_t* __restrict__ Cs_lo, int N, int K, int doRelu,
             const int* __restrict__ lens)
{
    extern __shared__ uint32_t sm[];
    const uint32_t sbase = smem_u32(sm);

    const int bm   = blockIdx.y * 128;
    if ((bm & (SS - 1)) >= lens[bm >> 9]) return;

    const int tid  = threadIdx.x;
    const int lane = tid & 31;
    const int warp = tid >> 5;
    const int g    = lane >> 2;
    const int tig  = lane & 3;
    const int wm   = warp >> 2;
    const int wn   = warp & 3;
    const int bn   = blockIdx.x * 128;
    const int Kw   = K >> 1;

    const int cr = tid >> 2;
    const int cc = (tid & 3) << 2;

    float acc[4][4][4];
    #pragma unroll
    for (int i = 0; i < 4; i++)
        #pragma unroll
        for (int j = 0; j < 4; j++)
            #pragma unroll
            for (int r = 0; r < 4; r++) acc[i][j][r] = 0.f;

    const int nChunks = K >> 5;

    const uint32_t* srcA_hi = A_hi + (size_t)(bm + cr) * Kw + cc;
    const uint32_t* srcA_lo = A_lo + (size_t)(bm + cr) * Kw + cc;
    const uint32_t* srcB_hi = W_hi + (size_t)(bn + cr) * Kw + cc;
    const uint32_t* srcB_lo = W_lo + (size_t)(bn + cr) * Kw + cc;
    const size_t rstep = (size_t)64 * Kw;

    #define ISSUE(stage, c) do {                                               \
        uint32_t db = sbase + (uint32_t)((stage) * STG) * 4;                   \
        int kw0 = (c) * 16;                                                    \
        uint32_t d0 = db + (uint32_t)(cr * RS + cc) * 4;                       \
        uint32_t d1 = db + (uint32_t)((cr + 64) * RS + cc) * 4;                \
        cp16(d0,              srcA_hi + kw0);                                  \
        cp16(d1,              srcA_hi + kw0 + rstep);                          \
        cp16(d0 + 2560 * 4,   srcA_lo + kw0);                                  \
        cp16(d1 + 2560 * 4,   srcA_lo + kw0 + rstep);                          \
        cp16(d0 + 5120 * 4,   srcB_hi + kw0);                                  \
        cp16(d1 + 5120 * 4,   srcB_hi + kw0 + rstep);                          \
        cp16(d0 + 7680 * 4,   srcB_lo + kw0);                                  \
        cp16(d1 + 7680 * 4,   srcB_lo + kw0 + rstep);                          \
        cp_commit();                                                           \
    } while (0)

    ISSUE(0, 0);

    for (int c = 0; c < nChunks; c++) {
        if (c + 1 < nChunks) { ISSUE((c + 1) & 1, c + 1); cp_wait1(); }
        else                 { cp_wait0(); }
        __syncthreads();

        const uint32_t* S   = sm + (c & 1) * STG;
        const uint32_t* sAh = S;
        const uint32_t* sAl = S + 2560;
        const uint32_t* sBh = S + 5120;
        const uint32_t* sBl = S + 7680;

        #pragma unroll
        for (int h = 0; h < 2; h++) {
            const int cA = h * 8 + tig;
            uint32_t ah[4][4], al[4][4], bh[4][2], bl[4][2];
            #pragma unroll
            for (int i = 0; i < 4; i++) {
                int m = (wm * 64 + i * 16 + g) * RS + cA;
                ah[i][0] = sAh[m];               ah[i][1] = sAh[m + 8 * RS];
                ah[i][2] = sAh[m + 4];           ah[i][3] = sAh[m + 8 * RS + 4];
                al[i][0] = sAl[m];               al[i][1] = sAl[m + 8 * RS];
                al[i][2] = sAl[m + 4];           al[i][3] = sAl[m + 8 * RS + 4];
            }
            #pragma unroll
            for (int j = 0; j < 4; j++) {
                int n = (wn * 32 + j * 8 + g) * RS + cA;
                bh[j][0] = sBh[n];  bh[j][1] = sBh[n + 4];
                bl[j][0] = sBl[n];  bl[j][1] = sBl[n + 4];
            }
            #pragma unroll
            for (int j = 0; j < 4; j++)
                #pragma unroll
                for (int i = 0; i < 4; i++) {
                    mma16816(acc[i][j], ah[i], bh[j]);
                    mma16816(acc[i][j], al[i], bh[j]);
                    mma16816(acc[i][j], ah[i], bl[j]);
                }
        }
        __syncthreads();
    }

    const int Nw = N >> 1;
    #pragma unroll
    for (int i = 0; i < 4; i++) {
        int r0 = bm + wm * 64 + i * 16 + g;
        int r1 = r0 + 8;
        #pragma unroll
        for (int j = 0; j < 4; j++) {
            int cix = bn + wn * 32 + j * 8 + tig * 2;
            float b0 = bias[cix], b1 = bias[cix + 1];
            float v0 = acc[i][j][0] + b0, v1 = acc[i][j][1] + b1;
            float v2 = acc[i][j][2] + b0, v3 = acc[i][j][3] + b1;
            if (pos) {
                int s0 = r0 & (SS - 1), s1 = r1 & (SS - 1);
                v0 += pos[(size_t)s0 * N + cix];
                v1 += pos[(size_t)s0 * N + cix + 1];
                v2 += pos[(size_t)s1 * N + cix];
                v3 += pos[(size_t)s1 * N + cix + 1];
            }
            if (doRelu) {
                v0 = fmaxf(v0, 0.f); v1 = fmaxf(v1, 0.f);
                v2 = fmaxf(v2, 0.f); v3 = fmaxf(v3, 0.f);
            }
            if (C) {
                *(float2*)(C + (size_t)r0 * N + cix) = make_float2(v0, v1);
                *(float2*)(C + (size_t)r1 * N + cix) = make_float2(v2, v3);
            }
            if (Cs_hi) {
                size_t w0 = (size_t)r0 * Nw + (cix >> 1);
                size_t w1 = (size_t)r1 * Nw + (cix >> 1);
                float h0 = __bfloat162float(__float2bfloat16_rn(v0));
                float h1 = __bfloat162float(__float2bfloat16_rn(v1));
                float h2 = __bfloat162float(__float2bfloat16_rn(v2));
                float h3 = __bfloat162float(__float2bfloat16_rn(v3));
                Cs_hi[w0] = pack_bf16(h0, h1);
                Cs_lo[w0] = pack_bf16(v0 - h0, v1 - h1);
                Cs_hi[w1] = pack_bf16(h2, h3);
                Cs_lo[w1] = pack_bf16(v2 - h2, v3 - h3);
            }
        }
    }
}

// -------------------- big GEMM: BK=64, ldmatrix, 16-row dead-skip -----------
#define BRS  36
#define ARRB (128 * BRS * 4)    // 18432 B per array
#define STGB (4 * ARRB)         // 73728 B per stage
#define GB_SMEM (2 * STGB)      // 147456 B

__global__ __launch_bounds__(256)
void gemm_big(const uint32_t* __restrict__ A_hi, const uint32_t* __restrict__ A_lo,
              const uint32_t* __restrict__ W_hi, const uint32_t* __restrict__ W_lo,
              const float* __restrict__ bias, float* __restrict__ C,
              uint32_t* __restrict__ Cs_hi, uint32_t* __restrict__ Cs_lo,
              int N, int K, int doRelu, const int* __restrict__ lens)
{
    extern __shared__ uint32_t sm[];
    const uint32_t ab = smem_u32(sm);

    const int bm   = blockIdx.y * 128;
    const int mlen = lens[bm >> 9] - (bm & (SS - 1));  // rows alive in this tile
    if (mlen <= 0) return;

    const int tid  = threadIdx.x;
    const int lane = tid & 31;
    const int warp = tid >> 5;
    const int g    = lane >> 2;
    const int tig  = lane & 3;
    const int wm   = warp >> 2;
    const int wn   = warp & 3;
    const int bn   = blockIdx.x * 128;
    const int Kw   = K >> 1;
    const int nCh  = K >> 6;
    const int mrem = mlen - wm * 64;       // live rows in this warp's half
    const bool mact = mrem > 0;
    bool act[4];
    #pragma unroll
    for (int i = 0; i < 4; i++) act[i] = (i * 16) < mrem;  // 16-row i-tile alive

    float acc[4][4][4];
    #pragma unroll
    for (int i = 0; i < 4; i++)
        #pragma unroll
        for (int j = 0; j < 4; j++)
            #pragma unroll
            for (int r = 0; r < 4; r++) acc[i][j][r] = 0.f;

    #define ISSUE2(stage, c) do {                                              \
        const uint32_t sb = ab + (uint32_t)(stage) * STGB;                     \
        _Pragma("unroll")                                                      \
        for (int t = 0; t < 16; t++) {                                         \
            int idx = tid + t * 256;                                           \
            int arr = idx >> 10;                                               \
            int rem = idx & 1023;                                              \
            int r   = rem >> 3;                                                \
            int u   = rem & 7;                                                 \
            const uint32_t* base = (arr == 0) ? A_hi : (arr == 1) ? A_lo       \
                                 : (arr == 2) ? W_hi : W_lo;                   \
            int row = ((arr < 2) ? bm : bn) + r;                               \
            cp16(sb + (uint32_t)arr * ARRB + (uint32_t)(r * BRS + u * 4) * 4,  \
                 base + (size_t)row * Kw + (c) * 32 + u * 4);                  \
        }                                                                      \
        cp_commit();                                                           \
    } while (0)

    ISSUE2(0, 0);

    const int l15 = lane & 15;
    const int lc4 = (lane >> 4) * 4;
    const int l7  = lane & 7;
    const int lb4 = ((lane >> 3) & 1) * 4;

    for (int c = 0; c < nCh; c++) {
        if (c + 1 < nCh) { ISSUE2((c + 1) & 1, c + 1); cp_wait1(); }
        else             { cp_wait0(); }
        __syncthreads();

        if (mact) {
            const uint32_t stb = ab + (uint32_t)(c & 1) * STGB;
            #pragma unroll
            for (int h = 0; h < 4; h++) {
                uint32_t ah[4][4], al[4][4], bh[4][2], bl[4][2];
                #pragma unroll
                for (int i = 0; i < 4; i++) {
                    if (act[i]) {
                        uint32_t ad = stb +
                            (uint32_t)((wm * 64 + i * 16 + l15) * BRS + h * 8 + lc4) * 4;
                        ldsm4(ah[i], ad);
                        ldsm4(al[i], ad + ARRB);
                    }
                }
                #pragma unroll
                for (int j = 0; j < 4; j++) {
                    uint32_t bd = stb + 2u * ARRB +
                        (uint32_t)((wn * 32 + j * 8 + l7) * BRS + h * 8 + lb4) * 4;
                    ldsm2(bh[j], bd);
                    ldsm2(bl[j], bd + ARRB);
                }
                #pragma unroll
                for (int j = 0; j < 4; j++)
                    #pragma unroll
                    for (int i = 0; i < 4; i++) {
                        if (act[i]) {
                            mma16816(acc[i][j], ah[i], bh[j]);
                            mma16816(acc[i][j], al[i], bh[j]);
                            mma16816(acc[i][j], ah[i], bl[j]);
                        }
                    }
            }
        }
        __syncthreads();
    }

    const int Nw = N >> 1;
    #pragma unroll
    for (int i = 0; i < 4; i++) {
        int r0 = bm + wm * 64 + i * 16 + g;
        int r1 = r0 + 8;
        #pragma unroll
        for (int j = 0; j < 4; j++) {
            int cix = bn + wn * 32 + j * 8 + tig * 2;
            float b0 = bias[cix], b1 = bias[cix + 1];
            float v0 = acc[i][j][0] + b0, v1 = acc[i][j][1] + b1;
            float v2 = acc[i][j][2] + b0, v3 = acc[i][j][3] + b1;
            if (doRelu) {
                v0 = fmaxf(v0, 0.f); v1 = fmaxf(v1, 0.f);
                v2 = fmaxf(v2, 0.f); v3 = fmaxf(v3, 0.f);
            }
            if (C) {
                *(float2*)(C + (size_t)r0 * N + cix) = make_float2(v0, v1);
                *(float2*)(C + (size_t)r1 * N + cix) = make_float2(v2, v3);
            }
            if (Cs_hi) {
                size_t w0 = (size_t)r0 * Nw + (cix >> 1);
                size_t w1 = (size_t)r1 * Nw + (cix >> 1);
                float h0 = __bfloat162float(__float2bfloat16_rn(v0));
                float h1 = __bfloat162float(__float2bfloat16_rn(v1));
                float h2 = __bfloat162float(__float2bfloat16_rn(v2));
                float h3 = __bfloat162float(__float2bfloat16_rn(v3));
                Cs_hi[w0] = pack_bf16(h0, h1);
                Cs_lo[w0] = pack_bf16(v0 - h0, v1 - h1);
                Cs_hi[w1] = pack_bf16(h2, h3);
                Cs_lo[w1] = pack_bf16(v2 - h2, v3 - h3);
            }
        }
    }
}

// -------------------- tensor-core attention (direct V via ldmatrix.trans) ---
#define AT_KH  0
#define AT_KL  18432
#define AT_QH  36864
#define AT_QL  38016
#define AT_PH  39168
#define AT_PL  47488
#define AT_RED 55808
#define AT_WORDS 56320
#define ATTN_SMEM (AT_WORDS * 4)

__global__ __launch_bounds__(256)
void attn_tc(const uint32_t* __restrict__ qh, const uint32_t* __restrict__ ql,
             const uint32_t* __restrict__ kh, const uint32_t* __restrict__ kl,
             const uint32_t* __restrict__ vh, const uint32_t* __restrict__ vl,
             const int* __restrict__ lens, float* __restrict__ O, int rst)
{
    extern __shared__ uint32_t sm[];
    const uint32_t sbase = smem_u32(sm);

    const int qt = blockIdx.x, h = blockIdx.y, b = blockIdx.z;
    const int len  = lens[b];
    if (qt * 32 >= len) return;

    const int tid  = threadIdx.x;
    const int lane = tid & 31;
    const int warp = tid >> 5;
    const int g    = lane >> 2;
    const int tig  = lane & 3;
    const int qbase = b * SS + qt * 32;
    const int nc   = (len + 15) >> 4;
    const int vrows = nc << 4;   // PV consumes rows [0, vrows); all finite in gmem
    const int l15  = lane & 15;
    const int lc4  = (lane >> 4) * 4;
    const int l7   = lane & 7;
    const int lb4  = ((lane >> 3) & 1) * 4;

    {
        int row = tid >> 3, ch = tid & 7;
        cp16(sbase + (uint32_t)(AT_QH + row * 36 + ch * 4) * 4,
             qh + (size_t)(qbase + row) * rst + h * 32 + ch * 4);
        cp16(sbase + (uint32_t)(AT_QL + row * 36 + ch * 4) * 4,
             ql + (size_t)(qbase + row) * rst + h * 32 + ch * 4);
    }
    for (int t = tid; t < 4096; t += 256) {
        int row = t >> 3, ch = t & 7;
        if (row < len) {
            cp16(sbase + (uint32_t)(AT_KH + row * 36 + ch * 4) * 4,
                 kh + (size_t)(b * SS + row) * rst + h * 32 + ch * 4);
            cp16(sbase + (uint32_t)(AT_KL + row * 36 + ch * 4) * 4,
                 kl + (size_t)(b * SS + row) * rst + h * 32 + ch * 4);
        }
    }
    cp_commit(); cp_wait0();
    __syncthreads();

    float acc[2][8][4];
    #pragma unroll
    for (int i = 0; i < 2; i++)
        #pragma unroll
        for (int j = 0; j < 8; j++)
            #pragma unroll
            for (int r = 0; r < 4; r++) acc[i][j][r] = 0.f;

    if (warp * 64 < len) {
        #pragma unroll
        for (int c = 0; c < 4; c++) {
            uint32_t ah[2][4], al[2][4];
            #pragma unroll
            for (int i = 0; i < 2; i++) {
                uint32_t ad = sbase +
                    (uint32_t)(AT_QH + (i * 16 + l15) * 36 + c * 8 + lc4) * 4;
                ldsm4(ah[i], ad);
                ldsm4(al[i], ad + (AT_QL - AT_QH) * 4);
            }
            #pragma unroll
            for (int j = 0; j < 8; j++) {
                uint32_t bd = sbase +
                    (uint32_t)(AT_KH + (warp * 64 + j * 8 + l7) * 36 + c * 8 + lb4) * 4;
                uint32_t bh[2], bl[2];
                ldsm2(bh, bd);
                ldsm2(bl, bd + (AT_KL - AT_KH) * 4);
                #pragma unroll
                for (int i = 0; i < 2; i++) {
                    mma16816(acc[i][j], ah[i], bh);
                    mma16816(acc[i][j], al[i], bh);
                    mma16816(acc[i][j], ah[i], bl);
                }
            }
        }
    }

    const float scale = 0.125f;
    #pragma unroll
    for (int i = 0; i < 2; i++)
        #pragma unroll
        for (int j = 0; j < 8; j++) {
            int c0 = warp * 64 + j * 8 + tig * 2;
            bool m0 = c0 < len, m1 = (c0 + 1) < len;
            acc[i][j][0] = m0 ? acc[i][j][0] * scale : -1e9f;
            acc[i][j][1] = m1 ? acc[i][j][1] * scale : -1e9f;
            acc[i][j][2] = m0 ? acc[i][j][2] * scale : -1e9f;
            acc[i][j][3] = m1 ? acc[i][j][3] * scale : -1e9f;
        }

    float* redM = (float*)(sm + AT_RED);
    float* redS = redM + 256;

    float rmax[2][2];
    #pragma unroll
    for (int i = 0; i < 2; i++)
        #pragma unroll
        for (int sub = 0; sub < 2; sub++) {
            float m = -1e30f;
            #pragma unroll
            for (int j = 0; j < 8; j++) {
                m = fmaxf(m, acc[i][j][2 * sub]);
                m = fmaxf(m, acc[i][j][2 * sub + 1]);
            }
            m = fmaxf(m, __shfl_xor_sync(0xffffffffu, m, 1));
            m = fmaxf(m, __shfl_xor_sync(0xffffffffu, m, 2));
            if (tig == 0) redM[(i * 16 + sub * 8 + g) * 8 + warp] = m;
        }
    __syncthreads();
    #pragma unroll
    for (int i = 0; i < 2; i++)
        #pragma unroll
        for (int sub = 0; sub < 2; sub++) {
            int row = i * 16 + sub * 8 + g;
            float m = -1e30f;
            #pragma unroll
            for (int w = 0; w < 8; w++) m = fmaxf(m, redM[row * 8 + w]);
            rmax[i][sub] = m;
        }

    #pragma unroll
    for (int i = 0; i < 2; i++)
        #pragma unroll
        for (int sub = 0; sub < 2; sub++) {
            float s = 0.f;
            #pragma unroll
            for (int j = 0; j < 8; j++) {
                float e0 = __expf(acc[i][j][2 * sub]     - rmax[i][sub]);
                float e1 = __expf(acc[i][j][2 * sub + 1] - rmax[i][sub]);
                acc[i][j][2 * sub] = e0; acc[i][j][2 * sub + 1] = e1;
                s += e0 + e1;
            }
            s += __shfl_xor_sync(0xffffffffu, s, 1);
            s += __shfl_xor_sync(0xffffffffu, s, 2);
            if (tig == 0) redS[(i * 16 + sub * 8 + g) * 8 + warp] = s;
        }
    __syncthreads();

    #pragma unroll
    for (int i = 0; i < 2; i++)
        #pragma unroll
        for (int sub = 0; sub < 2; sub++) {
            int row = i * 16 + sub * 8 + g;
            float s = 0.f;
            #pragma unroll
            for (int w = 0; w < 8; w++) s += redS[row * 8 + w];
            float inv = 1.f / s;
            #pragma unroll
            for (int j = 0; j < 8; j++) {
                float p0 = acc[i][j][2 * sub] * inv;
                float p1 = acc[i][j][2 * sub + 1] * inv;
                float h0 = __bfloat162float(__float2bfloat16_rn(p0));
                float h1 = __bfloat162float(__float2bfloat16_rn(p1));
                int wi = row * 260 + warp * 32 + j * 4 + tig;
                sm[AT_PH + wi] = pack_bf16(h0, h1);
                sm[AT_PL + wi] = pack_bf16(p0 - h0, p1 - h1);
            }
        }
    __syncthreads();

    // load V (row-major [s][d], same layout as K) over the K region.
    // rows < vrows (= 16*nc): PV tail reads [len, vrows) multiplied by P==0,
    // and gmem there is finite — avoids uninitialized-smem NaN poisoning.
    for (int t = tid; t < 4096; t += 256) {
        int row = t >> 3, ch = t & 7;
        if (row < vrows) {
            cp16(sbase + (uint32_t)(AT_KH + row * 36 + ch * 4) * 4,
                 vh + (size_t)(b * SS + row) * rst + h * 32 + ch * 4);
            cp16(sbase + (uint32_t)(AT_KL + row * 36 + ch * 4) * 4,
                 vl + (size_t)(b * SS + row) * rst + h * 32 + ch * 4);
        }
    }
    cp_commit(); cp_wait0();
    __syncthreads();

    // PV: B fragments via ldmatrix.x2.trans on V[s][d]
    const int wm2 = warp >> 2, wn2 = warp & 3;
    float oacc[2][4];
    #pragma unroll
    for (int j = 0; j < 2; j++)
        #pragma unroll
        for (int r = 0; r < 4; r++) oacc[j][r] = 0.f;

    #pragma unroll 4
    for (int c = 0; c < nc; c++) {
        uint32_t ah[4], al[4];
        uint32_t ad = sbase +
            (uint32_t)(AT_PH + (wm2 * 16 + l15) * 260 + c * 8 + lc4) * 4;
        ldsm4(ah, ad);
        ldsm4(al, ad + (AT_PL - AT_PH) * 4);
        #pragma unroll
        for (int j = 0; j < 2; j++) {
            uint32_t vd = sbase + (uint32_t)(AT_KH + (c * 16 + l15) * 36) * 4
                        + (uint32_t)(wn2 * 16 + j * 8) * 2;
            uint32_t bh[2], bl[2];
            ldsm2t(bh, vd);
            ldsm2t(bl, vd + (AT_KL - AT_KH) * 4);
            mma16816(oacc[j], ah, bh);
            mma16816(oacc[j], al, bh);
            mma16816(oacc[j], ah, bl);
        }
    }

    #pragma unroll
    for (int j = 0; j < 2; j++) {
        int col = h * DHD + wn2 * 16 + j * 8 + tig * 2;
        int r0 = qbase + wm2 * 16 + g;
        int r1 = r0 + 8;
        *(float2*)(O + (size_t)r0 * DD + col) = make_float2(oacc[j][0], oacc[j][1]);
        *(float2*)(O + (size_t)r1 * DD + col) = make_float2(oacc[j][2], oacc[j][3]);
    }
}

// -------------------- fused residual + LayerNorm + split (one-pass) ---------
__global__ __launch_bounds__(192)
void add_ln(const float* __restrict__ x, const float* __restrict__ y,
            const float* __restrict__ g, const float* __restrict__ bt,
            float* __restrict__ out, uint32_t* __restrict__ s_hi,
            uint32_t* __restrict__ s_lo, const int* __restrict__ lens)
{
    const int row = blockIdx.x;
    if ((row & (SS - 1)) >= lens[row >> 9]) return;
    const int tid = threadIdx.x;
    const int c0 = tid * 4;
    float4 xv = *(const float4*)(x + (size_t)row * DD + c0);
    float4 yv = *(const float4*)(y + (size_t)row * DD + c0);
    float v0 = xv.x + yv.x, v1 = xv.y + yv.y, v2 = xv.z + yv.z, v3 = xv.w + yv.w;
    float s  = v0 + v1 + v2 + v3;
    float sq = v0 * v0 + v1 * v1 + v2 * v2 + v3 * v3;
    blockReduceSum2(s, sq);
    float mean = s * (1.0f / DD);
    float var  = sq * (1.0f / DD) - mean * mean;
    float rstd = rsqrtf(var + 1e-5f);
    float d0 = v0 - mean, d1 = v1 - mean, d2 = v2 - mean, d3 = v3 - mean;
    float4 gv = *(const float4*)(g + c0);
    float4 bv = *(const float4*)(bt + c0);
    float o0 = d0 * rstd * gv.x + bv.x;
    float o1 = d1 * rstd * gv.y + bv.y;
    float o2 = d2 * rstd * gv.z + bv.z;
    float o3 = d3 * rstd * gv.w + bv.w;
    *(float4*)(out + (size_t)row * DD + c0) = make_float4(o0, o1, o2, o3);
    float h0 = __bfloat162float(__float2bfloat16_rn(o0));
    float h1 = __bfloat162float(__float2bfloat16_rn(o1));
    float h2 = __bfloat162float(__float2bfloat16_rn(o2));
    float h3 = __bfloat162float(__float2bfloat16_rn(o3));
    size_t w = (size_t)row * (DD / 2) + tid * 2;
    s_hi[w]     = pack_bf16(h0, h1);
    s_lo[w]     = pack_bf16(o0 - h0, o1 - h1);
    s_hi[w + 1] = pack_bf16(h2, h3);
    s_lo[w + 1] = pack_bf16(o2 - h2, o3 - h3);
}

// -------------------- masked mean pool + output projection -------------------
__global__ __launch_bounds__(256)
void pool_out(const float* __restrict__ hbuf, const int* __restrict__ lens,
              const float* __restrict__ ow, const float* __restrict__ ob,
              float* __restrict__ out)
{
    __shared__ float ps[8][DD];
    const int b = blockIdx.x;
    const int tid = threadIdx.x;
    const int warp = tid >> 5, lane = tid & 31;
    const int len = lens[b];
    float r[24];
    #pragma unroll
    for (int i = 0; i < 24; i++) r[i] = 0.f;
    for (int sp = warp; sp < len; sp += 8) {
        const float* row = hbuf + (size_t)(b * SS + sp) * DD;
        #pragma unroll
        for (int i = 0; i < 24; i++) r[i] += row[i * 32 + lane];
    }
    #pragma unroll
    for (int i = 0; i < 24; i++) ps[warp][i * 32 + lane] = r[i];
    __syncthreads();
    const float inv = 1.0f / (float)len;
    float acc = 0.f;
    #pragma unroll
    for (int i = 0; i < 3; i++) {
        int d = tid + i * 256;
        float s = 0.f;
        #pragma unroll
        for (int w = 0; w < 8; w++) s += ps[w][d];
        acc += s * inv * ow[d];
    }
    float tot = blockReduceSum(acc);
    if (tid == 0) out[b] = tot + ob[0];
}

// -------------------- launcher --------------------
extern "C" void kernel_launch(void* const* d_in, const int* in_sizes, int n_in,
                              void* d_out, int out_size)
{
    const float* x    = (const float*)d_in[0];
    const int*   lens = (const int*)  d_in[1];
    const float* in_w = (const float*)d_in[2];
    const float* in_b = (const float*)d_in[3];
    const float* pos  = (const float*)d_in[4];
    const float* qw   = (const float*)d_in[5];
    const float* qb   = (const float*)d_in[6];
    const float* kw   = (const float*)d_in[7];
    const float* kb   = (const float*)d_in[8];
    const float* vw   = (const float*)d_in[9];
    const float* vb   = (const float*)d_in[10];
    const float* w1   = (const float*)d_in[11];
    const float* b1   = (const float*)d_in[12];
    const float* w2   = (const float*)d_in[13];
    const float* b2   = (const float*)d_in[14];
    const float* ln1g = (const float*)d_in[15];
    const float* ln1b = (const float*)d_in[16];
    const float* ln2g = (const float*)d_in[17];
    const float* ln2b = (const float*)d_in[18];
    const float* ow   = (const float*)d_in[19];
    const float* ob   = (const float*)d_in[20];
    float* out = (float*)d_out;

    float *h, *o, *qkvb;
    uint32_t *xs_hi, *xs_lo, *hs_hi, *hs_lo, *ff_hi, *ff_lo, *w_hi, *w_lo;
    uint32_t *qkv_hi, *qkv_lo;
    cudaGetSymbolAddress((void**)&h,  g_h);
    cudaGetSymbolAddress((void**)&o,  g_o);
    cudaGetSymbolAddress((void**)&qkvb, g_qkvb);
    cudaGetSymbolAddress((void**)&xs_hi, g_xs_hi);
    cudaGetSymbolAddress((void**)&xs_lo, g_xs_lo);
    cudaGetSymbolAddress((void**)&hs_hi, g_hs_hi);
    cudaGetSymbolAddress((void**)&hs_lo, g_hs_lo);
    cudaGetSymbolAddress((void**)&ff_hi, g_ff_hi);
    cudaGetSymbolAddress((void**)&ff_lo, g_ff_lo);
    cudaGetSymbolAddress((void**)&qkv_hi, g_qkv_hi);
    cudaGetSymbolAddress((void**)&qkv_lo, g_qkv_lo);
    cudaGetSymbolAddress((void**)&w_hi,  g_w_hi);
    cudaGetSymbolAddress((void**)&w_lo,  g_w_lo);

    cudaFuncSetAttribute(gemm_tc, cudaFuncAttributeMaxDynamicSharedMemorySize,
                         GEMM_SMEM);
    cudaFuncSetAttribute(gemm_big, cudaFuncAttributeMaxDynamicSharedMemorySize,
                         GB_SMEM);
    cudaFuncSetAttribute(attn_tc, cudaFuncAttributeMaxDynamicSharedMemorySize,
                         ATTN_SMEM);

    const long QKV_L = 3L * DD * DD / 2;
    const long FFN_L = (long)DD * DFF_ / 2;

    const dim3 gD(DD / 128, MROWS / 128);
    const dim3 gQKV(3 * DD / 128, MROWS / 128);
    const dim3 gF(DFF_ / 128, MROWS / 128);
    const dim3 gA(SS / 32, HH, BB);

    xsplit<<<(MROWS * INF_ / 2 + 255) / 256, 256>>>(x, xs_hi, xs_lo, MROWS * INF_ / 2);
    wsplit<<<dim3(DD/64, 1, 1), 256>>>(in_w, w_hi + W_INW, w_lo + W_INW,
                                       INF_, DD, 12288);
    gemm_tc<<<gD, 256, GEMM_SMEM>>>(xs_hi, xs_lo, w_hi + W_INW, w_lo + W_INW,
                                    in_b, pos, h, hs_hi, hs_lo, DD, INF_, 0, lens);
    catb<<<(LL * 3 * DD + 255) / 256, 256>>>(qb, kb, vb, qkvb);
    wsplit3<<<dim3(DD/64, DD/64, 3*LL), 256>>>(qw, kw, vw, w_hi + W_QKV, w_lo + W_QKV);

    for (int l = 0; l < LL; l++) {
        const size_t woQ = (size_t)l * QKV_L;
        const size_t woF = (size_t)l * FFN_L;
        const size_t bo  = (size_t)l * DD;
        gemm_big<<<gQKV, 256, GB_SMEM>>>(hs_hi, hs_lo,
                                         w_hi + W_QKV + woQ, w_lo + W_QKV + woQ,
                                         qkvb + (size_t)l * 3 * DD, nullptr,
                                         qkv_hi, qkv_lo, 3 * DD, DD, 0, lens);
        if (l == 0) {
            wsplit<<<dim3(DFF_/64, DD/64, LL), 256>>>(w1, w_hi + W_W1, w_lo + W_W1,
                                                      DD, DFF_, FFN_L);
            wsplit<<<dim3(DD/64, DFF_/64, LL), 256>>>(w2, w_hi + W_W2, w_lo + W_W2,
                                                      DFF_, DD, FFN_L);
        }
        attn_tc<<<gA, 256, ATTN_SMEM>>>(qkv_hi, qkv_lo,
                                        qkv_hi + (DD / 2), qkv_lo + (DD / 2),
                                        qkv_hi + 2 * (DD / 2), qkv_lo + 2 * (DD / 2),
                                        lens, o, 3 * DD / 2);
        add_ln<<<MROWS, 192>>>(h, o, ln1g + bo, ln1b + bo, h, hs_hi, hs_lo, lens);
        gemm_big<<<gF, 256, GB_SMEM>>>(hs_hi, hs_lo,
                                       w_hi + W_W1 + woF, w_lo + W_W1 + woF,
                                       b1 + (size_t)l * DFF_, nullptr,
                                       ff_hi, ff_lo, DFF_, DD, 1, lens);
        gemm_big<<<gD, 256, GB_SMEM>>>(ff_hi, ff_lo,
                                       w_hi + W_W2 + woF, w_lo + W_W2 + woF,
                                       b2 + bo, o, nullptr, nullptr, DD, DFF_, 0, lens);
        add_ln<<<MROWS, 192>>>(h, o, ln2g + bo, ln2b + bo, h, hs_hi, hs_lo, lens);
    }

    pool_out<<<BB, 256>>>(h, lens, ow, ob, out);
}

// round 15
// speedup vs baseline: 1.0006x; 1.0006x over previous
#include <cuda_runtime.h>
#include <cuda_bf16.h>
#include <math.h>
#include <stdint.h>

// Problem constants
#define BB   16
#define SS   512
#define INF_ 32
#define DD   768
#define HH   12
#define LL   6
#define DHD  64
#define DFF_ 3072
#define MROWS (BB*SS)   // 8192

// -------------------- device scratch --------------------
__device__ float g_h [MROWS*DD];
__device__ float g_o [MROWS*DD];

__device__ uint32_t g_xs_hi[MROWS*INF_/2],  g_xs_lo[MROWS*INF_/2];
__device__ uint32_t g_hs_hi[MROWS*DD/2],    g_hs_lo[MROWS*DD/2];
__device__ uint32_t g_ff_hi[MROWS*DFF_/2],  g_ff_lo[MROWS*DFF_/2];
__device__ uint32_t g_qkv_hi[MROWS*3*DD/2], g_qkv_lo[MROWS*3*DD/2];
__device__ float    g_qkvb[LL*3*DD];

// split + transposed weights ([N][K/2] words per tensor)
#define W_INW 0
#define W_QKV 12288                       // L x [2304][384], layer stride 884736
#define W_W1  5320704                     // L x [3072][384], layer stride 1179648
#define W_W2  12398592                    // L x [768][1536], layer stride 1179648
#define W_TOT 19476480
__device__ uint32_t g_w_hi[W_TOT];
__device__ uint32_t g_w_lo[W_TOT];

// -------------------- helpers --------------------
__device__ __forceinline__ uint32_t pack_bf16(float x, float y) {
    __nv_bfloat162 t = __floats2bfloat162_rn(x, y);
    return *reinterpret_cast<uint32_t*>(&t);
}

__device__ __forceinline__ float blockReduceSum(float val) {
    __shared__ float sh[8];
    __syncthreads();
    int lane = threadIdx.x & 31, warp = threadIdx.x >> 5;
    int nw = blockDim.x >> 5;
    #pragma unroll
    for (int o = 16; o; o >>= 1) val += __shfl_xor_sync(0xffffffffu, val, o);
    if (lane == 0) sh[warp] = val;
    __syncthreads();
    if (warp == 0) {
        float v = (lane < nw) ? sh[lane] : 0.f;
        #pragma unroll
        for (int o = 4; o; o >>= 1) v += __shfl_xor_sync(0xffffffffu, v, o);
        if (lane == 0) sh[0] = v;
    }
    __syncthreads();
    return sh[0];
}

// fused 2-value block reduce (single barrier round); call once per kernel
__device__ __forceinline__ void blockReduceSum2(float& a, float& b) {
    __shared__ float sh[16];
    int lane = threadIdx.x & 31, warp = threadIdx.x >> 5;
    int nw = blockDim.x >> 5;
    #pragma unroll
    for (int o = 16; o; o >>= 1) {
        a += __shfl_xor_sync(0xffffffffu, a, o);
        b += __shfl_xor_sync(0xffffffffu, b, o);
    }
    if (lane == 0) { sh[warp] = a; sh[warp + 8] = b; }
    __syncthreads();
    if (warp == 0) {
        float va = (lane < nw) ? sh[lane] : 0.f;
        float vb = (lane < nw) ? sh[lane + 8] : 0.f;
        #pragma unroll
        for (int o = 4; o; o >>= 1) {
            va += __shfl_xor_sync(0xffffffffu, va, o);
            vb += __shfl_xor_sync(0xffffffffu, vb, o);
        }
        if (lane == 0) { sh[0] = va; sh[8] = vb; }
    }
    __syncthreads();
    a = sh[0]; b = sh[8];
}

__device__ __forceinline__ void mma16816(float* d, const uint32_t* a, const uint32_t* b) {
    asm volatile(
        "mma.sync.aligned.m16n8k16.row.col.f32.bf16.bf16.f32 "
        "{%0,%1,%2,%3}, {%4,%5,%6,%7}, {%8,%9}, {%0,%1,%2,%3};\n"
        : "+f"(d[0]), "+f"(d[1]), "+f"(d[2]), "+f"(d[3])
        : "r"(a[0]), "r"(a[1]), "r"(a[2]), "r"(a[3]), "r"(b[0]), "r"(b[1]));
}

__device__ __forceinline__ void ldsm4(uint32_t* r, uint32_t addr) {
    asm volatile("ldmatrix.sync.aligned.m8n8.x4.shared.b16 {%0,%1,%2,%3}, [%4];"
                 : "=r"(r[0]), "=r"(r[1]), "=r"(r[2]), "=r"(r[3]) : "r"(addr));
}
__device__ __forceinline__ void ldsm2(uint32_t* r, uint32_t addr) {
    asm volatile("ldmatrix.sync.aligned.m8n8.x2.shared.b16 {%0,%1}, [%2];"
                 : "=r"(r[0]), "=r"(r[1]) : "r"(addr));
}
__device__ __forceinline__ void ldsm2t(uint32_t* r, uint32_t addr) {
    asm volatile("ldmatrix.sync.aligned.m8n8.x2.trans.shared.b16 {%0,%1}, [%2];"
                 : "=r"(r[0]), "=r"(r[1]) : "r"(addr));
}

__device__ __forceinline__ void cp16(uint32_t dst, const void* src) {
    asm volatile("cp.async.cg.shared.global [%0], [%1], 16;\n" :: "r"(dst), "l"(src));
}
__device__ __forceinline__ void cp_commit() { asm volatile("cp.async.commit_group;\n"); }
__device__ __forceinline__ void cp_wait0()  { asm volatile("cp.async.wait_group 0;\n"); }
__device__ __forceinline__ void cp_wait1()  { asm volatile("cp.async.wait_group 1;\n"); }

__device__ __forceinline__ uint32_t smem_u32(const void* p) {
    return (uint32_t)__cvta_generic_to_shared(p);
}

// -------------------- weight transpose + split (vectorized) -----------------
__device__ __forceinline__ void wsplit_body(
    const float* __restrict__ W, uint32_t* __restrict__ hi,
    uint32_t* __restrict__ lo, int K, int N, int n0, int k0, int tid,
    float (*t)[65])
{
    #pragma unroll
    for (int i = 0; i < 4; i++) {
        int idx = tid + i * 256;
        int k = idx >> 4, f = (idx & 15) * 4;
        if (k0 + k < K) {
            float4 v = *(const float4*)(W + (size_t)(k0 + k) * N + n0 + f);
            t[k][f] = v.x; t[k][f + 1] = v.y; t[k][f + 2] = v.z; t[k][f + 3] = v.w;
        }
    }
    __syncthreads();
    const int Kw = K >> 1;
    #pragma unroll
    for (int i = 0; i < 2; i++) {
        int idx = tid + i * 256;
        int n = idx >> 3, wq = idx & 7;
        if (k0 / 2 + wq * 4 < Kw) {
            uint32_t hh[4], ll[4];
            #pragma unroll
            for (int j = 0; j < 4; j++) {
                int kk = wq * 8 + j * 2;
                float a = t[kk][n], b = t[kk + 1][n];
                float ha = __bfloat162float(__float2bfloat16_rn(a));
                float hb = __bfloat162float(__float2bfloat16_rn(b));
                hh[j] = pack_bf16(ha, hb);
                ll[j] = pack_bf16(a - ha, b - hb);
            }
            size_t wi = (size_t)(n0 + n) * Kw + k0 / 2 + wq * 4;
            *(uint4*)(hi + wi) = make_uint4(hh[0], hh[1], hh[2], hh[3]);
            *(uint4*)(lo + wi) = make_uint4(ll[0], ll[1], ll[2], ll[3]);
        }
    }
}

__global__ __launch_bounds__(256)
void wsplit(const float* __restrict__ W, uint32_t* __restrict__ hi,
            uint32_t* __restrict__ lo, int K, int N, long lstr)
{
    __shared__ float t[64][65];
    const int l = blockIdx.z;
    wsplit_body(W + (size_t)l * K * N, hi + (size_t)l * lstr,
                lo + (size_t)l * lstr, K, N,
                blockIdx.x * 64, blockIdx.y * 64, threadIdx.x, t);
}

__global__ __launch_bounds__(256)
void wsplit3(const float* __restrict__ q, const float* __restrict__ k,
             const float* __restrict__ v, uint32_t* __restrict__ hi,
             uint32_t* __restrict__ lo)
{
    __shared__ float t[64][65];
    const int z = blockIdx.z, l = z / 3, t3 = z % 3;
    const float* W = (t3 == 0 ? q : (t3 == 1 ? k : v)) + (size_t)l * DD * DD;
    const size_t off = (size_t)l * (3L * DD * DD / 2) + (size_t)t3 * (DD * DD / 2);
    wsplit_body(W, hi + off, lo + off, DD, DD,
                blockIdx.x * 64, blockIdx.y * 64, threadIdx.x, t);
}

__global__ void xsplit(const float* __restrict__ src, uint32_t* __restrict__ hi,
                       uint32_t* __restrict__ lo, int nPairs)
{
    int i = blockIdx.x * blockDim.x + threadIdx.x;
    if (i < nPairs) {
        float2 v = *(const float2*)(src + 2 * i);
        float h0 = __bfloat162float(__float2bfloat16_rn(v.x));
        float h1 = __bfloat162float(__float2bfloat16_rn(v.y));
        hi[i] = pack_bf16(h0, h1);
        lo[i] = pack_bf16(v.x - h0, v.y - h1);
    }
}

__global__ void catb(const float* __restrict__ qb, const float* __restrict__ kb,
                     const float* __restrict__ vb, float* __restrict__ o)
{
    int idx = blockIdx.x * 256 + threadIdx.x;
    if (idx < LL * 3 * DD) {
        int l = idx / (3 * DD), r = idx % (3 * DD);
        float v = (r < DD) ? qb[l * DD + r]
                : (r < 2 * DD) ? kb[l * DD + r - DD] : vb[l * DD + r - 2 * DD];
        o[idx] = v;
    }
}

// -------------------- legacy bf16x2 GEMM (K=32 in-proj only) ----------------
#define RS 20
#define STG 10240
#define GEMM_SMEM (2 * STG * 4)

__global__ __launch_bounds__(256)
void gemm_tc(const uint32_t* __restrict__ A_hi, const uint32_t* __restrict__ A_lo,
             const uint32_t* __restrict__ W_hi, const uint32_t* __restrict__ W_lo,
             const float* __restrict__ bias, const float* __restrict__ pos,
             float* __restrict__ C, uint32_t* __restrict__ Cs_hi,
             uint32_t* __restrict__ Cs_lo, int N, int K, int doRelu,
             const int* __restrict__ lens)
{
    extern __shared__ uint32_t sm[];
    const uint32_t sbase = smem_u32(sm);

    const int bm   = blockIdx.y * 128;
    if ((bm & (SS - 1)) >= lens[bm >> 9]) return;

    const int tid  = threadIdx.x;
    const int lane = tid & 31;
    const int warp = tid >> 5;
    const int g    = lane >> 2;
    const int tig  = lane & 3;
    const int wm   = warp >> 2;
    const int wn   = warp & 3;
    const int bn   = blockIdx.x * 128;
    const int Kw   = K >> 1;

    const int cr = tid >> 2;
    const int cc = (tid & 3) << 2;

    float acc[4][4][4];
    #pragma unroll
    for (int i = 0; i < 4; i++)
        #pragma unroll
        for (int j = 0; j < 4; j++)
            #pragma unroll
            for (int r = 0; r < 4; r++) acc[i][j][r] = 0.f;

    const int nChunks = K >> 5;

    const uint32_t* srcA_hi = A_hi + (size_t)(bm + cr) * Kw + cc;
    const uint32_t* srcA_lo = A_lo + (size_t)(bm + cr) * Kw + cc;
    const uint32_t* srcB_hi = W_hi + (size_t)(bn + cr) * Kw + cc;
    const uint32_t* srcB_lo = W_lo + (size_t)(bn + cr) * Kw + cc;
    const size_t rstep = (size_t)64 * Kw;

    #define ISSUE(stage, c) do {                                               \
        uint32_t db = sbase + (uint32_t)((stage) * STG) * 4;                   \
        int kw0 = (c) * 16;                                                    \
        uint32_t d0 = db + (uint32_t)(cr * RS + cc) * 4;                       \
        uint32_t d1 = db + (uint32_t)((cr + 64) * RS + cc) * 4;                \
        cp16(d0,              srcA_hi + kw0);                                  \
        cp16(d1,              srcA_hi + kw0 + rstep);                          \
        cp16(d0 + 2560 * 4,   srcA_lo + kw0);                                  \
        cp16(d1 + 2560 * 4,   srcA_lo + kw0 + rstep);                          \
        cp16(d0 + 5120 * 4,   srcB_hi + kw0);                                  \
        cp16(d1 + 5120 * 4,   srcB_hi + kw0 + rstep);                          \
        cp16(d0 + 7680 * 4,   srcB_lo + kw0);                                  \
        cp16(d1 + 7680 * 4,   srcB_lo + kw0 + rstep);                          \
        cp_commit();                                                           \
    } while (0)

    ISSUE(0, 0);

    for (int c = 0; c < nChunks; c++) {
        if (c + 1 < nChunks) { ISSUE((c + 1) & 1, c + 1); cp_wait1(); }
        else                 { cp_wait0(); }
        __syncthreads();

        const uint32_t* S   = sm + (c & 1) * STG;
        const uint32_t* sAh = S;
        const uint32_t* sAl = S + 2560;
        const uint32_t* sBh = S + 5120;
        const uint32_t* sBl = S + 7680;

        #pragma unroll
        for (int h = 0; h < 2; h++) {
            const int cA = h * 8 + tig;
            uint32_t ah[4][4], al[4][4], bh[4][2], bl[4][2];
            #pragma unroll
            for (int i = 0; i < 4; i++) {
                int m = (wm * 64 + i * 16 + g) * RS + cA;
                ah[i][0] = sAh[m];               ah[i][1] = sAh[m + 8 * RS];
                ah[i][2] = sAh[m + 4];           ah[i][3] = sAh[m + 8 * RS + 4];
                al[i][0] = sAl[m];               al[i][1] = sAl[m + 8 * RS];
                al[i][2] = sAl[m + 4];           al[i][3] = sAl[m + 8 * RS + 4];
            }
            #pragma unroll
            for (int j = 0; j < 4; j++) {
                int n = (wn * 32 + j * 8 + g) * RS + cA;
                bh[j][0] = sBh[n];  bh[j][1] = sBh[n + 4];
                bl[j][0] = sBl[n];  bl[j][1] = sBl[n + 4];
            }
            #pragma unroll
            for (int j = 0; j < 4; j++)
                #pragma unroll
                for (int i = 0; i < 4; i++) {
                    mma16816(acc[i][j], ah[i], bh[j]);
                    mma16816(acc[i][j], al[i], bh[j]);
                    mma16816(acc[i][j], ah[i], bl[j]);
                }
        }
        __syncthreads();
    }

    const int Nw = N >> 1;
    #pragma unroll
    for (int i = 0; i < 4; i++) {
        int r0 = bm + wm * 64 + i * 16 + g;
        int r1 = r0 + 8;
        #pragma unroll
        for (int j = 0; j < 4; j++) {
            int cix = bn + wn * 32 + j * 8 + tig * 2;
            float b0 = bias[cix], b1 = bias[cix + 1];
            float v0 = acc[i][j][0] + b0, v1 = acc[i][j][1] + b1;
            float v2 = acc[i][j][2] + b0, v3 = acc[i][j][3] + b1;
            if (pos) {
                int s0 = r0 & (SS - 1), s1 = r1 & (SS - 1);
                v0 += pos[(size_t)s0 * N + cix];
                v1 += pos[(size_t)s0 * N + cix + 1];
                v2 += pos[(size_t)s1 * N + cix];
                v3 += pos[(size_t)s1 * N + cix + 1];
            }
            if (doRelu) {
                v0 = fmaxf(v0, 0.f); v1 = fmaxf(v1, 0.f);
                v2 = fmaxf(v2, 0.f); v3 = fmaxf(v3, 0.f);
            }
            if (C) {
                *(float2*)(C + (size_t)r0 * N + cix) = make_float2(v0, v1);
                *(float2*)(C + (size_t)r1 * N + cix) = make_float2(v2, v3);
            }
            if (Cs_hi) {
                size_t w0 = (size_t)r0 * Nw + (cix >> 1);
                size_t w1 = (size_t)r1 * Nw + (cix >> 1);
                float h0 = __bfloat162float(__float2bfloat16_rn(v0));
                float h1 = __bfloat162float(__float2bfloat16_rn(v1));
                float h2 = __bfloat162float(__float2bfloat16_rn(v2));
                float h3 = __bfloat162float(__float2bfloat16_rn(v3));
                Cs_hi[w0] = pack_bf16(h0, h1);
                Cs_lo[w0] = pack_bf16(v0 - h0, v1 - h1);
                Cs_hi[w1] = pack_bf16(h2, h3);
                Cs_lo[w1] = pack_bf16(v2 - h2, v3 - h3);
            }
        }
    }
}

// -------------------- big GEMM: BK=64, ldmatrix, 16-row dead-skip -----------
#define BRS  36
#define ARRB (128 * BRS * 4)    // 18432 B per array
#define STGB (4 * ARRB)         // 73728 B per stage
#define GB_SMEM (2 * STGB)      // 147456 B

__global__ __launch_bounds__(256)
void gemm_big(const uint32_t* __restrict__ A_hi, const uint32_t* __restrict__ A_lo,
              const uint32_t* __restrict__ W_hi, const uint32_t* __restrict__ W_lo,
              const float* __restrict__ bias, float* __restrict__ C,
              uint32_t* __restrict__ Cs_hi, uint32_t* __restrict__ Cs_lo,
              int N, int K, int doRelu, const int* __restrict__ lens)
{
    extern __shared__ uint32_t sm[];
    const uint32_t ab = smem_u32(sm);

    const int bm   = blockIdx.y * 128;
    const int mlen = lens[bm >> 9] - (bm & (SS - 1));  // rows alive in this tile
    if (mlen <= 0) return;

    const int tid  = threadIdx.x;
    const int lane = tid & 31;
    const int warp = tid >> 5;
    const int g    = lane >> 2;
    const int tig  = lane & 3;
    const int wm   = warp >> 2;
    const int wn   = warp & 3;
    const int bn   = blockIdx.x * 128;
    const int Kw   = K >> 1;
    const int nCh  = K >> 6;
    const int mrem = mlen - wm * 64;       // live rows in this warp's half
    const bool mact = mrem > 0;
    bool act[4];
    #pragma unroll
    for (int i = 0; i < 4; i++) act[i] = (i * 16) < mrem;  // 16-row i-tile alive

    float acc[4][4][4];
    #pragma unroll
    for (int i = 0; i < 4; i++)
        #pragma unroll
        for (int j = 0; j < 4; j++)
            #pragma unroll
            for (int r = 0; r < 4; r++) acc[i][j][r] = 0.f;

    #define ISSUE2(stage, c) do {                                              \
        const uint32_t sb = ab + (uint32_t)(stage) * STGB;                     \
        _Pragma("unroll")                                                      \
        for (int t = 0; t < 16; t++) {                                         \
            int idx = tid + t * 256;                                           \
            int arr = idx >> 10;                                               \
            int rem = idx & 1023;                                              \
            int r   = rem >> 3;                                                \
            int u   = rem & 7;                                                 \
            const uint32_t* base = (arr == 0) ? A_hi : (arr == 1) ? A_lo       \
                                 : (arr == 2) ? W_hi : W_lo;                   \
            int row = ((arr < 2) ? bm : bn) + r;                               \
            cp16(sb + (uint32_t)arr * ARRB + (uint32_t)(r * BRS + u * 4) * 4,  \
                 base + (size_t)row * Kw + (c) * 32 + u * 4);                  \
        }                                                                      \
        cp_commit();                                                           \
    } while (0)

    ISSUE2(0, 0);

    const int l15 = lane & 15;
    const int lc4 = (lane >> 4) * 4;
    const int l7  = lane & 7;
    const int lb4 = ((lane >> 3) & 1) * 4;

    for (int c = 0; c < nCh; c++) {
        if (c + 1 < nCh) { ISSUE2((c + 1) & 1, c + 1); cp_wait1(); }
        else             { cp_wait0(); }
        __syncthreads();

        if (mact) {
            const uint32_t stb = ab + (uint32_t)(c & 1) * STGB;
            #pragma unroll
            for (int h = 0; h < 4; h++) {
                uint32_t ah[4][4], al[4][4], bh[4][2], bl[4][2];
                #pragma unroll
                for (int i = 0; i < 4; i++) {
                    if (act[i]) {
                        uint32_t ad = stb +
                            (uint32_t)((wm * 64 + i * 16 + l15) * BRS + h * 8 + lc4) * 4;
                        ldsm4(ah[i], ad);
                        ldsm4(al[i], ad + ARRB);
                    }
                }
                #pragma unroll
                for (int j = 0; j < 4; j++) {
                    uint32_t bd = stb + 2u * ARRB +
                        (uint32_t)((wn * 32 + j * 8 + l7) * BRS + h * 8 + lb4) * 4;
                    ldsm2(bh[j], bd);
                    ldsm2(bl[j], bd + ARRB);
                }
                #pragma unroll
                for (int j = 0; j < 4; j++)
                    #pragma unroll
                    for (int i = 0; i < 4; i++) {
                        if (act[i]) {
                            mma16816(acc[i][j], ah[i], bh[j]);
                            mma16816(acc[i][j], al[i], bh[j]);
                            mma16816(acc[i][j], ah[i], bl[j]);
                        }
                    }
            }
        }
        __syncthreads();
    }

    const int Nw = N >> 1;
    #pragma unroll
    for (int i = 0; i < 4; i++) {
        int r0 = bm + wm * 64 + i * 16 + g;
        int r1 = r0 + 8;
        #pragma unroll
        for (int j = 0; j < 4; j++) {
            int cix = bn + wn * 32 + j * 8 + tig * 2;
            float b0 = bias[cix], b1 = bias[cix + 1];
            float v0 = acc[i][j][0] + b0, v1 = acc[i][j][1] + b1;
            float v2 = acc[i][j][2] + b0, v3 = acc[i][j][3] + b1;
            if (doRelu) {
                v0 = fmaxf(v0, 0.f); v1 = fmaxf(v1, 0.f);
                v2 = fmaxf(v2, 0.f); v3 = fmaxf(v3, 0.f);
            }
            if (C) {
                *(float2*)(C + (size_t)r0 * N + cix) = make_float2(v0, v1);
                *(float2*)(C + (size_t)r1 * N + cix) = make_float2(v2, v3);
            }
            if (Cs_hi) {
                size_t w0 = (size_t)r0 * Nw + (cix >> 1);
                size_t w1 = (size_t)r1 * Nw + (cix >> 1);
                float h0 = __bfloat162float(__float2bfloat16_rn(v0));
                float h1 = __bfloat162float(__float2bfloat16_rn(v1));
                float h2 = __bfloat162float(__float2bfloat16_rn(v2));
                float h3 = __bfloat162float(__float2bfloat16_rn(v3));
                Cs_hi[w0] = pack_bf16(h0, h1);
                Cs_lo[w0] = pack_bf16(v0 - h0, v1 - h1);
                Cs_hi[w1] = pack_bf16(h2, h3);
                Cs_lo[w1] = pack_bf16(v2 - h2, v3 - h3);
            }
        }
    }
}

// -------------------- tensor-core attention (direct V via ldmatrix.trans) ---
#define AT_KH  0
#define AT_KL  18432
#define AT_QH  36864
#define AT_QL  38016
#define AT_PH  39168
#define AT_PL  47488
#define AT_RED 55808
#define AT_WORDS 56320
#define ATTN_SMEM (AT_WORDS * 4)

__global__ __launch_bounds__(256)
void attn_tc(const uint32_t* __restrict__ qh, const uint32_t* __restrict__ ql,
             const uint32_t* __restrict__ kh, const uint32_t* __restrict__ kl,
             const uint32_t* __restrict__ vh, const uint32_t* __restrict__ vl,
             const int* __restrict__ lens, float* __restrict__ O, int rst)
{
    extern __shared__ uint32_t sm[];
    const uint32_t sbase = smem_u32(sm);

    const int qt = blockIdx.x, h = blockIdx.y, b = blockIdx.z;
    const int len  = lens[b];
    if (qt * 32 >= len) return;

    const int tid  = threadIdx.x;
    const int lane = tid & 31;
    const int warp = tid >> 5;
    const int g    = lane >> 2;
    const int tig  = lane & 3;
    const int qbase = b * SS + qt * 32;
    const int nc   = (len + 15) >> 4;
    const int vrows = nc << 4;   // PV consumes rows [0, vrows); all finite in gmem
    const int l15  = lane & 15;
    const int lc4  = (lane >> 4) * 4;
    const int l7   = lane & 7;
    const int lb4  = ((lane >> 3) & 1) * 4;

    {
        int row = tid >> 3, ch = tid & 7;
        cp16(sbase + (uint32_t)(AT_QH + row * 36 + ch * 4) * 4,
             qh + (size_t)(qbase + row) * rst + h * 32 + ch * 4);
        cp16(sbase + (uint32_t)(AT_QL + row * 36 + ch * 4) * 4,
             ql + (size_t)(qbase + row) * rst + h * 32 + ch * 4);
    }
    for (int t = tid; t < 4096; t += 256) {
        int row = t >> 3, ch = t & 7;
        if (row < len) {
            cp16(sbase + (uint32_t)(AT_KH + row * 36 + ch * 4) * 4,
                 kh + (size_t)(b * SS + row) * rst + h * 32 + ch * 4);
            cp16(sbase + (uint32_t)(AT_KL + row * 36 + ch * 4) * 4,
                 kl + (size_t)(b * SS + row) * rst + h * 32 + ch * 4);
        }
    }
    cp_commit(); cp_wait0();
    __syncthreads();

    float acc[2][8][4];
    #pragma unroll
    for (int i = 0; i < 2; i++)
        #pragma unroll
        for (int j = 0; j < 8; j++)
            #pragma unroll
            for (int r = 0; r < 4; r++) acc[i][j][r] = 0.f;

    if (warp * 64 < len) {
        #pragma unroll
        for (int c = 0; c < 4; c++) {
            uint32_t ah[2][4], al[2][4];
            #pragma unroll
            for (int i = 0; i < 2; i++) {
                uint32_t ad = sbase +
                    (uint32_t)(AT_QH + (i * 16 + l15) * 36 + c * 8 + lc4) * 4;
                ldsm4(ah[i], ad);
                ldsm4(al[i], ad + (AT_QL - AT_QH) * 4);
            }
            #pragma unroll
            for (int j = 0; j < 8; j++) {
                uint32_t bd = sbase +
                    (uint32_t)(AT_KH + (warp * 64 + j * 8 + l7) * 36 + c * 8 + lb4) * 4;
                uint32_t bh[2], bl[2];
                ldsm2(bh, bd);
                ldsm2(bl, bd + (AT_KL - AT_KH) * 4);
                #pragma unroll
                for (int i = 0; i < 2; i++) {
                    mma16816(acc[i][j], ah[i], bh);
                    mma16816(acc[i][j], al[i], bh);
                    mma16816(acc[i][j], ah[i], bl);
                }
            }
        }
    }

    const float scale = 0.125f;
    #pragma unroll
    for (int i = 0; i < 2; i++)
        #pragma unroll
        for (int j = 0; j < 8; j++) {
            int c0 = warp * 64 + j * 8 + tig * 2;
            bool m0 = c0 < len, m1 = (c0 + 1) < len;
            acc[i][j][0] = m0 ? acc[i][j][0] * scale : -1e9f;
            acc[i][j][1] = m1 ? acc[i][j][1] * scale : -1e9f;
            acc[i][j][2] = m0 ? acc[i][j][2] * scale : -1e9f;
            acc[i][j][3] = m1 ? acc[i][j][3] * scale : -1e9f;
        }

    float* redM = (float*)(sm + AT_RED);
    float* redS = redM + 256;

    float rmax[2][2];
    #pragma unroll
    for (int i = 0; i < 2; i++)
        #pragma unroll
        for (int sub = 0; sub < 2; sub++) {
            float m = -1e30f;
            #pragma unroll
            for (int j = 0; j < 8; j++) {
                m = fmaxf(m, acc[i][j][2 * sub]);
                m = fmaxf(m, acc[i][j][2 * sub + 1]);
            }
            m = fmaxf(m, __shfl_xor_sync(0xffffffffu, m, 1));
            m = fmaxf(m, __shfl_xor_sync(0xffffffffu, m, 2));
            if (tig == 0) redM[(i * 16 + sub * 8 + g) * 8 + warp] = m;
        }
    __syncthreads();
    #pragma unroll
    for (int i = 0; i < 2; i++)
        #pragma unroll
        for (int sub = 0; sub < 2; sub++) {
            int row = i * 16 + sub * 8 + g;
            float m = -1e30f;
            #pragma unroll
            for (int w = 0; w < 8; w++) m = fmaxf(m, redM[row * 8 + w]);
            rmax[i][sub] = m;
        }

    #pragma unroll
    for (int i = 0; i < 2; i++)
        #pragma unroll
        for (int sub = 0; sub < 2; sub++) {
            float s = 0.f;
            #pragma unroll
            for (int j = 0; j < 8; j++) {
                float e0 = __expf(acc[i][j][2 * sub]     - rmax[i][sub]);
                float e1 = __expf(acc[i][j][2 * sub + 1] - rmax[i][sub]);
                acc[i][j][2 * sub] = e0; acc[i][j][2 * sub + 1] = e1;
                s += e0 + e1;
            }
            s += __shfl_xor_sync(0xffffffffu, s, 1);
            s += __shfl_xor_sync(0xffffffffu, s, 2);
            if (tig == 0) redS[(i * 16 + sub * 8 + g) * 8 + warp] = s;
        }
    __syncthreads();

    #pragma unroll
    for (int i = 0; i < 2; i++)
        #pragma unroll
        for (int sub = 0; sub < 2; sub++) {
            int row = i * 16 + sub * 8 + g;
            float s = 0.f;
            #pragma unroll
            for (int w = 0; w < 8; w++) s += redS[row * 8 + w];
            float inv = 1.f / s;
            #pragma unroll
            for (int j = 0; j < 8; j++) {
                float p0 = acc[i][j][2 * sub] * inv;
                float p1 = acc[i][j][2 * sub + 1] * inv;
                float h0 = __bfloat162float(__float2bfloat16_rn(p0));
                float h1 = __bfloat162float(__float2bfloat16_rn(p1));
                int wi = row * 260 + warp * 32 + j * 4 + tig;
                sm[AT_PH + wi] = pack_bf16(h0, h1);
                sm[AT_PL + wi] = pack_bf16(p0 - h0, p1 - h1);
            }
        }
    __syncthreads();

    // load V (row-major [s][d], same layout as K) over the K region.
    // rows < vrows (= 16*nc): PV tail reads [len, vrows) multiplied by P==0,
    // and gmem there is finite — avoids uninitialized-smem NaN poisoning.
    for (int t = tid; t < 4096; t += 256) {
        int row = t >> 3, ch = t & 7;
        if (row < vrows) {
            cp16(sbase + (uint32_t)(AT_KH + row * 36 + ch * 4) * 4,
                 vh + (size_t)(b * SS + row) * rst + h * 32 + ch * 4);
            cp16(sbase + (uint32_t)(AT_KL + row * 36 + ch * 4) * 4,
                 vl + (size_t)(b * SS + row) * rst + h * 32 + ch * 4);
        }
    }
    cp_commit(); cp_wait0();
    __syncthreads();

    // PV: B fragments via ldmatrix.x2.trans on V[s][d]
    const int wm2 = warp >> 2, wn2 = warp & 3;
    float oacc[2][4];
    #pragma unroll
    for (int j = 0; j < 2; j++)
        #pragma unroll
        for (int r = 0; r < 4; r++) oacc[j][r] = 0.f;

    #pragma unroll 4
    for (int c = 0; c < nc; c++) {
        uint32_t ah[4], al[4];
        uint32_t ad = sbase +
            (uint32_t)(AT_PH + (wm2 * 16 + l15) * 260 + c * 8 + lc4) * 4;
        ldsm4(ah, ad);
        ldsm4(al, ad + (AT_PL - AT_PH) * 4);
        #pragma unroll
        for (int j = 0; j < 2; j++) {
            uint32_t vd = sbase + (uint32_t)(AT_KH + (c * 16 + l15) * 36) * 4
                        + (uint32_t)(wn2 * 16 + j * 8) * 2;
            uint32_t bh[2], bl[2];
            ldsm2t(bh, vd);
            ldsm2t(bl, vd + (AT_KL - AT_KH) * 4);
            mma16816(oacc[j], ah, bh);
            mma16816(oacc[j], al, bh);
            mma16816(oacc[j], ah, bl);
        }
    }

    #pragma unroll
    for (int j = 0; j < 2; j++) {
        int col = h * DHD + wn2 * 16 + j * 8 + tig * 2;
        int r0 = qbase + wm2 * 16 + g;
        int r1 = r0 + 8;
        *(float2*)(O + (size_t)r0 * DD + col) = make_float2(oacc[j][0], oacc[j][1]);
        *(float2*)(O + (size_t)r1 * DD + col) = make_float2(oacc[j][2], oacc[j][3]);
    }
}

// -------------------- fused residual + LayerNorm + split (one-pass) ---------
__global__ __launch_bounds__(192)
void add_ln(const float* __restrict__ x, const float* __restrict__ y,
            const float* __restrict__ g, const float* __restrict__ bt,
            float* __restrict__ out, uint32_t* __restrict__ s_hi,
            uint32_t* __restrict__ s_lo, const int* __restrict__ lens)
{
    const int row = blockIdx.x;
    if ((row & (SS - 1)) >= lens[row >> 9]) return;
    const int tid = threadIdx.x;
    const int c0 = tid * 4;
    float4 xv = *(const float4*)(x + (size_t)row * DD + c0);
    float4 yv = *(const float4*)(y + (size_t)row * DD + c0);
    float v0 = xv.x + yv.x, v1 = xv.y + yv.y, v2 = xv.z + yv.z, v3 = xv.w + yv.w;
    float s  = v0 + v1 + v2 + v3;
    float sq = v0 * v0 + v1 * v1 + v2 * v2 + v3 * v3;
    blockReduceSum2(s, sq);
    float mean = s * (1.0f / DD);
    float var  = sq * (1.0f / DD) - mean * mean;
    float rstd = rsqrtf(var + 1e-5f);
    float d0 = v0 - mean, d1 = v1 - mean, d2 = v2 - mean, d3 = v3 - mean;
    float4 gv = *(const float4*)(g + c0);
    float4 bv = *(const float4*)(bt + c0);
    float o0 = d0 * rstd * gv.x + bv.x;
    float o1 = d1 * rstd * gv.y + bv.y;
    float o2 = d2 * rstd * gv.z + bv.z;
    float o3 = d3 * rstd * gv.w + bv.w;
    *(float4*)(out + (size_t)row * DD + c0) = make_float4(o0, o1, o2, o3);
    float h0 = __bfloat162float(__float2bfloat16_rn(o0));
    float h1 = __bfloat162float(__float2bfloat16_rn(o1));
    float h2 = __bfloat162float(__float2bfloat16_rn(o2));
    float h3 = __bfloat162float(__float2bfloat16_rn(o3));
    size_t w = (size_t)row * (DD / 2) + tid * 2;
    s_hi[w]     = pack_bf16(h0, h1);
    s_lo[w]     = pack_bf16(o0 - h0, o1 - h1);
    s_hi[w + 1] = pack_bf16(h2, h3);
    s_lo[w + 1] = pack_bf16(o2 - h2, o3 - h3);
}

// -------------------- masked mean pool + output projection -------------------
__global__ __launch_bounds__(256)
void pool_out(const float* __restrict__ hbuf, const int* __restrict__ lens,
              const float* __restrict__ ow, const float* __restrict__ ob,
              float* __restrict__ out)
{
    __shared__ float ps[8][DD];
    const int b = blockIdx.x;
    const int tid = threadIdx.x;
    const int warp = tid >> 5, lane = tid & 31;
    const int len = lens[b];
    float r[24];
    #pragma unroll
    for (int i = 0; i < 24; i++) r[i] = 0.f;
    for (int sp = warp; sp < len; sp += 8) {
        const float* row = hbuf + (size_t)(b * SS + sp) * DD;
        #pragma unroll
        for (int i = 0; i < 24; i++) r[i] += row[i * 32 + lane];
    }
    #pragma unroll
    for (int i = 0; i < 24; i++) ps[warp][i * 32 + lane] = r[i];
    __syncthreads();
    const float inv = 1.0f / (float)len;
    float acc = 0.f;
    #pragma unroll
    for (int i = 0; i < 3; i++) {
        int d = tid + i * 256;
        float s = 0.f;
        #pragma unroll
        for (int w = 0; w < 8; w++) s += ps[w][d];
        acc += s * inv * ow[d];
    }
    float tot = blockReduceSum(acc);
    if (tid == 0) out[b] = tot + ob[0];
}

// -------------------- launcher --------------------
extern "C" void kernel_launch(void* const* d_in, const int* in_sizes, int n_in,
                              void* d_out, int out_size)
{
    const float* x    = (const float*)d_in[0];
    const int*   lens = (const int*)  d_in[1];
    const float* in_w = (const float*)d_in[2];
    const float* in_b = (const float*)d_in[3];
    const float* pos  = (const float*)d_in[4];
    const float* qw   = (const float*)d_in[5];
    const float* qb   = (const float*)d_in[6];
    const float* kw   = (const float*)d_in[7];
    const float* kb   = (const float*)d_in[8];
    const float* vw   = (const float*)d_in[9];
    const float* vb   = (const float*)d_in[10];
    const float* w1   = (const float*)d_in[11];
    const float* b1   = (const float*)d_in[12];
    const float* w2   = (const float*)d_in[13];
    const float* b2   = (const float*)d_in[14];
    const float* ln1g = (const float*)d_in[15];
    const float* ln1b = (const float*)d_in[16];
    const float* ln2g = (const float*)d_in[17];
    const float* ln2b = (const float*)d_in[18];
    const float* ow   = (const float*)d_in[19];
    const float* ob   = (const float*)d_in[20];
    float* out = (float*)d_out;

    float *h, *o, *qkvb;
    uint32_t *xs_hi, *xs_lo, *hs_hi, *hs_lo, *ff_hi, *ff_lo, *w_hi, *w_lo;
    uint32_t *qkv_hi, *qkv_lo;
    cudaGetSymbolAddress((void**)&h,  g_h);
    cudaGetSymbolAddress((void**)&o,  g_o);
    cudaGetSymbolAddress((void**)&qkvb, g_qkvb);
    cudaGetSymbolAddress((void**)&xs_hi, g_xs_hi);
    cudaGetSymbolAddress((void**)&xs_lo, g_xs_lo);
    cudaGetSymbolAddress((void**)&hs_hi, g_hs_hi);
    cudaGetSymbolAddress((void**)&hs_lo, g_hs_lo);
    cudaGetSymbolAddress((void**)&ff_hi, g_ff_hi);
    cudaGetSymbolAddress((void**)&ff_lo, g_ff_lo);
    cudaGetSymbolAddress((void**)&qkv_hi, g_qkv_hi);
    cudaGetSymbolAddress((void**)&qkv_lo, g_qkv_lo);
    cudaGetSymbolAddress((void**)&w_hi,  g_w_hi);
    cudaGetSymbolAddress((void**)&w_lo,  g_w_lo);

    cudaFuncSetAttribute(gemm_tc, cudaFuncAttributeMaxDynamicSharedMemorySize,
                         GEMM_SMEM);
    cudaFuncSetAttribute(gemm_big, cudaFuncAttributeMaxDynamicSharedMemorySize,
                         GB_SMEM);
    cudaFuncSetAttribute(attn_tc, cudaFuncAttributeMaxDynamicSharedMemorySize,
                         ATTN_SMEM);

    const long QKV_L = 3L * DD * DD / 2;
    const long FFN_L = (long)DD * DFF_ / 2;

    const dim3 gD(DD / 128, MROWS / 128);
    const dim3 gQKV(3 * DD / 128, MROWS / 128);
    const dim3 gF(DFF_ / 128, MROWS / 128);
    const dim3 gA(SS / 32, HH, BB);

    xsplit<<<(MROWS * INF_ / 2 + 255) / 256, 256>>>(x, xs_hi, xs_lo, MROWS * INF_ / 2);
    wsplit<<<dim3(DD/64, 1, 1), 256>>>(in_w, w_hi + W_INW, w_lo + W_INW,
                                       INF_, DD, 12288);
    gemm_tc<<<gD, 256, GEMM_SMEM>>>(xs_hi, xs_lo, w_hi + W_INW, w_lo + W_INW,
                                    in_b, pos, h, hs_hi, hs_lo, DD, INF_, 0, lens);
    catb<<<(LL * 3 * DD + 255) / 256, 256>>>(qb, kb, vb, qkvb);
    wsplit3<<<dim3(DD/64, DD/64, 3*LL), 256>>>(qw, kw, vw, w_hi + W_QKV, w_lo + W_QKV);

    for (int l = 0; l < LL; l++) {
        const size_t woQ = (size_t)l * QKV_L;
        const size_t woF = (size_t)l * FFN_L;
        const size_t bo  = (size_t)l * DD;
        gemm_big<<<gQKV, 256, GB_SMEM>>>(hs_hi, hs_lo,
                                         w_hi + W_QKV + woQ, w_lo + W_QKV + woQ,
                                         qkvb + (size_t)l * 3 * DD, nullptr,
                                         qkv_hi, qkv_lo, 3 * DD, DD, 0, lens);
        if (l == 0) {
            wsplit<<<dim3(DFF_/64, DD/64, LL), 256>>>(w1, w_hi + W_W1, w_lo + W_W1,
                                                      DD, DFF_, FFN_L);
            wsplit<<<dim3(DD/64, DFF_/64, LL), 256>>>(w2, w_hi + W_W2, w_lo + W_W2,
                                                      DFF_, DD, FFN_L);
        }
        attn_tc<<<gA, 256, ATTN_SMEM>>>(qkv_hi, qkv_lo,
                                        qkv_hi + (DD / 2), qkv_lo + (DD / 2),
                                        qkv_hi + 2 * (DD / 2), qkv_lo + 2 * (DD / 2),
                                        lens, o, 3 * DD / 2);
        add_ln<<<MROWS, 192>>>(h, o, ln1g + bo, ln1b + bo, h, hs_hi, hs_lo, lens);
        gemm_big<<<gF, 256, GB_SMEM>>>(hs_hi, hs_lo,
                                       w_hi + W_W1 + woF, w_lo + W_W1 + woF,
                                       b1 + (size_t)l * DFF_, nullptr,
                                       ff_hi, ff_lo, DFF_, DD, 1, lens);
        gemm_big<<<gD, 256, GB_SMEM>>>(ff_hi, ff_lo,
                                       w_hi + W_W2 + woF, w_lo + W_W2 + woF,
                                       b2 + bo, o, nullptr, nullptr, DD, DFF_, 0, lens);
        add_ln<<<MROWS, 192>>>(h, o, ln2g + bo, ln2b + bo, h, hs_hi, hs_lo, lens);
    }

    pool_out<<<BB, 256>>>(h, lens, ow, ob, out);
}

// round 16
// speedup vs baseline: 1.1939x; 1.1932x over previous
#include <cuda_runtime.h>
#include <cuda_bf16.h>
#include <math.h>
#include <stdint.h>

// Problem constants
#define BB   16
#define SS   512
#define INF_ 32
#define DD   768
#define HH   12
#define LL   6
#define DHD  64
#define DFF_ 3072
#define MROWS (BB*SS)   // 8192

// -------------------- device scratch --------------------
__device__ float g_h [MROWS*DD];
__device__ float g_o [MROWS*DD];

__device__ uint32_t g_xs_hi[MROWS*INF_/2],  g_xs_lo[MROWS*INF_/2];
__device__ uint32_t g_hs_hi[MROWS*DD/2],    g_hs_lo[MROWS*DD/2];
__device__ uint32_t g_ff_hi[MROWS*DFF_/2],  g_ff_lo[MROWS*DFF_/2];
__device__ uint32_t g_qkv_hi[MROWS*3*DD/2], g_qkv_lo[MROWS*3*DD/2];
__device__ float    g_qkvb[LL*3*DD];

// split + transposed weights ([N][K/2] words per tensor)
#define W_INW 0
#define W_QKV 12288                       // L x [2304][384], layer stride 884736
#define W_W1  5320704                     // L x [3072][384], layer stride 1179648
#define W_W2  12398592                    // L x [768][1536], layer stride 1179648
#define W_TOT 19476480
__device__ uint32_t g_w_hi[W_TOT];
__device__ uint32_t g_w_lo[W_TOT];

// -------------------- helpers --------------------
__device__ __forceinline__ uint32_t pack_bf16(float x, float y) {
    __nv_bfloat162 t = __floats2bfloat162_rn(x, y);
    return *reinterpret_cast<uint32_t*>(&t);
}

__device__ __forceinline__ float blockReduceSum(float val) {
    __shared__ float sh[8];
    __syncthreads();
    int lane = threadIdx.x & 31, warp = threadIdx.x >> 5;
    int nw = blockDim.x >> 5;
    #pragma unroll
    for (int o = 16; o; o >>= 1) val += __shfl_xor_sync(0xffffffffu, val, o);
    if (lane == 0) sh[warp] = val;
    __syncthreads();
    if (warp == 0) {
        float v = (lane < nw) ? sh[lane] : 0.f;
        #pragma unroll
        for (int o = 4; o; o >>= 1) v += __shfl_xor_sync(0xffffffffu, v, o);
        if (lane == 0) sh[0] = v;
    }
    __syncthreads();
    return sh[0];
}

// fused 2-value block reduce (single barrier round); call once per kernel
__device__ __forceinline__ void blockReduceSum2(float& a, float& b) {
    __shared__ float sh[16];
    int lane = threadIdx.x & 31, warp = threadIdx.x >> 5;
    int nw = blockDim.x >> 5;
    #pragma unroll
    for (int o = 16; o; o >>= 1) {
        a += __shfl_xor_sync(0xffffffffu, a, o);
        b += __shfl_xor_sync(0xffffffffu, b, o);
    }
    if (lane == 0) { sh[warp] = a; sh[warp + 8] = b; }
    __syncthreads();
    if (warp == 0) {
        float va = (lane < nw) ? sh[lane] : 0.f;
        float vb = (lane < nw) ? sh[lane + 8] : 0.f;
        #pragma unroll
        for (int o = 4; o; o >>= 1) {
            va += __shfl_xor_sync(0xffffffffu, va, o);
            vb += __shfl_xor_sync(0xffffffffu, vb, o);
        }
        if (lane == 0) { sh[0] = va; sh[8] = vb; }
    }
    __syncthreads();
    a = sh[0]; b = sh[8];
}

__device__ __forceinline__ void mma16816(float* d, const uint32_t* a, const uint32_t* b) {
    asm volatile(
        "mma.sync.aligned.m16n8k16.row.col.f32.bf16.bf16.f32 "
        "{%0,%1,%2,%3}, {%4,%5,%6,%7}, {%8,%9}, {%0,%1,%2,%3};\n"
        : "+f"(d[0]), "+f"(d[1]), "+f"(d[2]), "+f"(d[3])
        : "r"(a[0]), "r"(a[1]), "r"(a[2]), "r"(a[3]), "r"(b[0]), "r"(b[1]));
}

__device__ __forceinline__ void ldsm4(uint32_t* r, uint32_t addr) {
    asm volatile("ldmatrix.sync.aligned.m8n8.x4.shared.b16 {%0,%1,%2,%3}, [%4];"
                 : "=r"(r[0]), "=r"(r[1]), "=r"(r[2]), "=r"(r[3]) : "r"(addr));
}
__device__ __forceinline__ void ldsm2(uint32_t* r, uint32_t addr) {
    asm volatile("ldmatrix.sync.aligned.m8n8.x2.shared.b16 {%0,%1}, [%2];"
                 : "=r"(r[0]), "=r"(r[1]) : "r"(addr));
}
__device__ __forceinline__ void ldsm2t(uint32_t* r, uint32_t addr) {
    asm volatile("ldmatrix.sync.aligned.m8n8.x2.trans.shared.b16 {%0,%1}, [%2];"
                 : "=r"(r[0]), "=r"(r[1]) : "r"(addr));
}

__device__ __forceinline__ void cp16(uint32_t dst, const void* src) {
    asm volatile("cp.async.cg.shared.global [%0], [%1], 16;\n" :: "r"(dst), "l"(src));
}
__device__ __forceinline__ void cp_commit() { asm volatile("cp.async.commit_group;\n"); }
__device__ __forceinline__ void cp_wait0()  { asm volatile("cp.async.wait_group 0;\n"); }
__device__ __forceinline__ void cp_wait1()  { asm volatile("cp.async.wait_group 1;\n"); }

__device__ __forceinline__ uint32_t smem_u32(const void* p) {
    return (uint32_t)__cvta_generic_to_shared(p);
}

// -------------------- weight transpose + split (vectorized) -----------------
__device__ __forceinline__ void wsplit_body(
    const float* __restrict__ W, uint32_t* __restrict__ hi,
    uint32_t* __restrict__ lo, int K, int N, int n0, int k0, int tid,
    float (*t)[65])
{
    #pragma unroll
    for (int i = 0; i < 4; i++) {
        int idx = tid + i * 256;
        int k = idx >> 4, f = (idx & 15) * 4;
        if (k0 + k < K) {
            float4 v = *(const float4*)(W + (size_t)(k0 + k) * N + n0 + f);
            t[k][f] = v.x; t[k][f + 1] = v.y; t[k][f + 2] = v.z; t[k][f + 3] = v.w;
        }
    }
    __syncthreads();
    const int Kw = K >> 1;
    #pragma unroll
    for (int i = 0; i < 2; i++) {
        int idx = tid + i * 256;
        int n = idx >> 3, wq = idx & 7;
        if (k0 / 2 + wq * 4 < Kw) {
            uint32_t hh[4], ll[4];
            #pragma unroll
            for (int j = 0; j < 4; j++) {
                int kk = wq * 8 + j * 2;
                float a = t[kk][n], b = t[kk + 1][n];
                float ha = __bfloat162float(__float2bfloat16_rn(a));
                float hb = __bfloat162float(__float2bfloat16_rn(b));
                hh[j] = pack_bf16(ha, hb);
                ll[j] = pack_bf16(a - ha, b - hb);
            }
            size_t wi = (size_t)(n0 + n) * Kw + k0 / 2 + wq * 4;
            *(uint4*)(hi + wi) = make_uint4(hh[0], hh[1], hh[2], hh[3]);
            *(uint4*)(lo + wi) = make_uint4(ll[0], ll[1], ll[2], ll[3]);
        }
    }
}

__global__ __launch_bounds__(256)
void wsplit(const float* __restrict__ W, uint32_t* __restrict__ hi,
            uint32_t* __restrict__ lo, int K, int N, long lstr)
{
    __shared__ float t[64][65];
    const int l = blockIdx.z;
    wsplit_body(W + (size_t)l * K * N, hi + (size_t)l * lstr,
                lo + (size_t)l * lstr, K, N,
                blockIdx.x * 64, blockIdx.y * 64, threadIdx.x, t);
}

__global__ __launch_bounds__(256)
void wsplit3(const float* __restrict__ q, const float* __restrict__ k,
             const float* __restrict__ v, uint32_t* __restrict__ hi,
             uint32_t* __restrict__ lo)
{
    __shared__ float t[64][65];
    const int z = blockIdx.z, l = z / 3, t3 = z % 3;
    const float* W = (t3 == 0 ? q : (t3 == 1 ? k : v)) + (size_t)l * DD * DD;
    const size_t off = (size_t)l * (3L * DD * DD / 2) + (size_t)t3 * (DD * DD / 2);
    wsplit_body(W, hi + off, lo + off, DD, DD,
                blockIdx.x * 64, blockIdx.y * 64, threadIdx.x, t);
}

__global__ void xsplit(const float* __restrict__ src, uint32_t* __restrict__ hi,
                       uint32_t* __restrict__ lo, int nPairs)
{
    int i = blockIdx.x * blockDim.x + threadIdx.x;
    if (i < nPairs) {
        float2 v = *(const float2*)(src + 2 * i);
        float h0 = __bfloat162float(__float2bfloat16_rn(v.x));
        float h1 = __bfloat162float(__float2bfloat16_rn(v.y));
        hi[i] = pack_bf16(h0, h1);
        lo[i] = pack_bf16(v.x - h0, v.y - h1);
    }
}

__global__ void catb(const float* __restrict__ qb, const float* __restrict__ kb,
                     const float* __restrict__ vb, float* __restrict__ o)
{
    int idx = blockIdx.x * 256 + threadIdx.x;
    if (idx < LL * 3 * DD) {
        int l = idx / (3 * DD), r = idx % (3 * DD);
        float v = (r < DD) ? qb[l * DD + r]
                : (r < 2 * DD) ? kb[l * DD + r - DD] : vb[l * DD + r - 2 * DD];
        o[idx] = v;
    }
}

// -------------------- legacy bf16x2 GEMM (K=32 in-proj only) ----------------
#define RS 20
#define STG 10240
#define GEMM_SMEM (2 * STG * 4)

__global__ __launch_bounds__(256)
void gemm_tc(const uint32_t* __restrict__ A_hi, const uint32_t* __restrict__ A_lo,
             const uint32_t* __restrict__ W_hi, const uint32_t* __restrict__ W_lo,
             const float* __restrict__ bias, const float* __restrict__ pos,
             float* __restrict__ C, uint32_t* __restrict__ Cs_hi,
             uint32_t* __restrict__ Cs_lo, int N, int K, int doRelu,
             const int* __restrict__ lens)
{
    extern __shared__ uint32_t sm[];
    const uint32_t sbase = smem_u32(sm);

    const int bm   = blockIdx.y * 128;
    if ((bm & (SS - 1)) >= lens[bm >> 9]) return;

    const int tid  = threadIdx.x;
    const int lane = tid & 31;
    const int warp = tid >> 5;
    const int g    = lane >> 2;
    const int tig  = lane & 3;
    const int wm   = warp >> 2;
    const int wn   = warp & 3;
    const int bn   = blockIdx.x * 128;
    const int Kw   = K >> 1;

    const int cr = tid >> 2;
    const int cc = (tid & 3) << 2;

    float acc[4][4][4];
    #pragma unroll
    for (int i = 0; i < 4; i++)
        #pragma unroll
        for (int j = 0; j < 4; j++)
            #pragma unroll
            for (int r = 0; r < 4; r++) acc[i][j][r] = 0.f;

    const int nChunks = K >> 5;

    const uint32_t* srcA_hi = A_hi + (size_t)(bm + cr) * Kw + cc;
    const uint32_t* srcA_lo = A_lo + (size_t)(bm + cr) * Kw + cc;
    const uint32_t* srcB_hi = W_hi + (size_t)(bn + cr) * Kw + cc;
    const uint32_t* srcB_lo = W_lo + (size_t)(bn + cr) * Kw + cc;
    const size_t rstep = (size_t)64 * Kw;

    #define ISSUE(stage, c) do {                                               \
        uint32_t db = sbase + (uint32_t)((stage) * STG) * 4;                   \
        int kw0 = (c) * 16;                                                    \
        uint32_t d0 = db + (uint32_t)(cr * RS + cc) * 4;                       \
        uint32_t d1 = db + (uint32_t)((cr + 64) * RS + cc) * 4;                \
        cp16(d0,              srcA_hi + kw0);                                  \
        cp16(d1,              srcA_hi + kw0 + rstep);                          \
        cp16(d0 + 2560 * 4,   srcA_lo + kw0);                                  \
        cp16(d1 + 2560 * 4,   srcA_lo + kw0 + rstep);                          \
        cp16(d0 + 5120 * 4,   srcB_hi + kw0);                                  \
        cp16(d1 + 5120 * 4,   srcB_hi + kw0 + rstep);                          \
        cp16(d0 + 7680 * 4,   srcB_lo + kw0);                                  \
        cp16(d1 + 7680 * 4,   srcB_lo + kw0 + rstep);                          \
        cp_commit();                                                           \
    } while (0)

    ISSUE(0, 0);

    for (int c = 0; c < nChunks; c++) {
        if (c + 1 < nChunks) { ISSUE((c + 1) & 1, c + 1); cp_wait1(); }
        else                 { cp_wait0(); }
        __syncthreads();

        const uint32_t* S   = sm + (c & 1) * STG;
        const uint32_t* sAh = S;
        const uint32_t* sAl = S + 2560;
        const uint32_t* sBh = S + 5120;
        const uint32_t* sBl = S + 7680;

        #pragma unroll
        for (int h = 0; h < 2; h++) {
            const int cA = h * 8 + tig;
            uint32_t ah[4][4], al[4][4], bh[4][2], bl[4][2];
            #pragma unroll
            for (int i = 0; i < 4; i++) {
                int m = (wm * 64 + i * 16 + g) * RS + cA;
                ah[i][0] = sAh[m];               ah[i][1] = sAh[m + 8 * RS];
                ah[i][2] = sAh[m + 4];           ah[i][3] = sAh[m + 8 * RS + 4];
                al[i][0] = sAl[m];               al[i][1] = sAl[m + 8 * RS];
                al[i][2] = sAl[m + 4];           al[i][3] = sAl[m + 8 * RS + 4];
            }
            #pragma unroll
            for (int j = 0; j < 4; j++) {
                int n = (wn * 32 + j * 8 + g) * RS + cA;
                bh[j][0] = sBh[n];  bh[j][1] = sBh[n + 4];
                bl[j][0] = sBl[n];  bl[j][1] = sBl[n + 4];
            }
            #pragma unroll
            for (int j = 0; j < 4; j++)
                #pragma unroll
                for (int i = 0; i < 4; i++) {
                    mma16816(acc[i][j], ah[i], bh[j]);
                    mma16816(acc[i][j], al[i], bh[j]);
                    mma16816(acc[i][j], ah[i], bl[j]);
                }
        }
        __syncthreads();
    }

    const int Nw = N >> 1;
    #pragma unroll
    for (int i = 0; i < 4; i++) {
        int r0 = bm + wm * 64 + i * 16 + g;
        int r1 = r0 + 8;
        #pragma unroll
        for (int j = 0; j < 4; j++) {
            int cix = bn + wn * 32 + j * 8 + tig * 2;
            float b0 = bias[cix], b1 = bias[cix + 1];
            float v0 = acc[i][j][0] + b0, v1 = acc[i][j][1] + b1;
            float v2 = acc[i][j][2] + b0, v3 = acc[i][j][3] + b1;
            if (pos) {
                int s0 = r0 & (SS - 1), s1 = r1 & (SS - 1);
                v0 += pos[(size_t)s0 * N + cix];
                v1 += pos[(size_t)s0 * N + cix + 1];
                v2 += pos[(size_t)s1 * N + cix];
                v3 += pos[(size_t)s1 * N + cix + 1];
            }
            if (doRelu) {
                v0 = fmaxf(v0, 0.f); v1 = fmaxf(v1, 0.f);
                v2 = fmaxf(v2, 0.f); v3 = fmaxf(v3, 0.f);
            }
            if (C) {
                *(float2*)(C + (size_t)r0 * N + cix) = make_float2(v0, v1);
                *(float2*)(C + (size_t)r1 * N + cix) = make_float2(v2, v3);
            }
            if (Cs_hi) {
                size_t w0 = (size_t)r0 * Nw + (cix >> 1);
                size_t w1 = (size_t)r1 * Nw + (cix >> 1);
                float h0 = __bfloat162float(__float2bfloat16_rn(v0));
                float h1 = __bfloat162float(__float2bfloat16_rn(v1));
                float h2 = __bfloat162float(__float2bfloat16_rn(v2));
                float h3 = __bfloat162float(__float2bfloat16_rn(v3));
                Cs_hi[w0] = pack_bf16(h0, h1);
                Cs_lo[w0] = pack_bf16(v0 - h0, v1 - h1);
                Cs_hi[w1] = pack_bf16(h2, h3);
                Cs_lo[w1] = pack_bf16(v2 - h2, v3 - h3);
            }
        }
    }
}

// -------------------- big GEMM: BK=64, ldmatrix, two-path dead-skip ---------
#define BRS  36
#define ARRB (128 * BRS * 4)    // 18432 B per array
#define STGB (4 * ARRB)         // 73728 B per stage
#define GB_SMEM (2 * STGB)      // 147456 B

// unconditional chunk body over NI i-tiles (NI compile-time: 4 or 2)
#define GB_CHUNK(NI) do {                                                      \
    _Pragma("unroll")                                                          \
    for (int h = 0; h < 4; h++) {                                              \
        uint32_t ah[NI][4], al[NI][4], bh[4][2], bl[4][2];                     \
        _Pragma("unroll")                                                      \
        for (int i = 0; i < NI; i++) {                                         \
            uint32_t ad = stb +                                                \
                (uint32_t)((wm * 64 + i * 16 + l15) * BRS + h * 8 + lc4) * 4;  \
            ldsm4(ah[i], ad);                                                  \
            ldsm4(al[i], ad + ARRB);                                           \
        }                                                                      \
        _Pragma("unroll")                                                      \
        for (int j = 0; j < 4; j++) {                                          \
            uint32_t bd = stb + 2u * ARRB +                                    \
                (uint32_t)((wn * 32 + j * 8 + l7) * BRS + h * 8 + lb4) * 4;    \
            ldsm2(bh[j], bd);                                                  \
            ldsm2(bl[j], bd + ARRB);                                           \
        }                                                                      \
        _Pragma("unroll")                                                      \
        for (int j = 0; j < 4; j++)                                            \
            _Pragma("unroll")                                                  \
            for (int i = 0; i < NI; i++) {                                     \
                mma16816(acc[i][j], ah[i], bh[j]);                             \
                mma16816(acc[i][j], al[i], bh[j]);                             \
                mma16816(acc[i][j], ah[i], bl[j]);                             \
            }                                                                  \
    }                                                                          \
} while (0)

__global__ __launch_bounds__(256)
void gemm_big(const uint32_t* __restrict__ A_hi, const uint32_t* __restrict__ A_lo,
              const uint32_t* __restrict__ W_hi, const uint32_t* __restrict__ W_lo,
              const float* __restrict__ bias, float* __restrict__ C,
              uint32_t* __restrict__ Cs_hi, uint32_t* __restrict__ Cs_lo,
              int N, int K, int doRelu, const int* __restrict__ lens)
{
    extern __shared__ uint32_t sm[];
    const uint32_t ab = smem_u32(sm);

    const int bm   = blockIdx.y * 128;
    const int mlen = lens[bm >> 9] - (bm & (SS - 1));  // rows alive in this tile
    if (mlen <= 0) return;

    const int tid  = threadIdx.x;
    const int lane = tid & 31;
    const int warp = tid >> 5;
    const int g    = lane >> 2;
    const int tig  = lane & 3;
    const int wm   = warp >> 2;
    const int wn   = warp & 3;
    const int bn   = blockIdx.x * 128;
    const int Kw   = K >> 1;
    const int nCh  = K >> 6;
    const int mrem = mlen - wm * 64;       // live rows in this warp's half
    const bool full = mrem > 32;           // need all 4 i-tiles
    const bool half = mrem > 0 && mrem <= 32;  // only i-tiles 0,1

    float acc[4][4][4];
    #pragma unroll
    for (int i = 0; i < 4; i++)
        #pragma unroll
        for (int j = 0; j < 4; j++)
            #pragma unroll
            for (int r = 0; r < 4; r++) acc[i][j][r] = 0.f;

    #define ISSUE2(stage, c) do {                                              \
        const uint32_t sb = ab + (uint32_t)(stage) * STGB;                     \
        _Pragma("unroll")                                                      \
        for (int t = 0; t < 16; t++) {                                         \
            int idx = tid + t * 256;                                           \
            int arr = idx >> 10;                                               \
            int rem = idx & 1023;                                              \
            int r   = rem >> 3;                                                \
            int u   = rem & 7;                                                 \
            const uint32_t* base = (arr == 0) ? A_hi : (arr == 1) ? A_lo       \
                                 : (arr == 2) ? W_hi : W_lo;                   \
            int row = ((arr < 2) ? bm : bn) + r;                               \
            cp16(sb + (uint32_t)arr * ARRB + (uint32_t)(r * BRS + u * 4) * 4,  \
                 base + (size_t)row * Kw + (c) * 32 + u * 4);                  \
        }                                                                      \
        cp_commit();                                                           \
    } while (0)

    ISSUE2(0, 0);

    const int l15 = lane & 15;
    const int lc4 = (lane >> 4) * 4;
    const int l7  = lane & 7;
    const int lb4 = ((lane >> 3) & 1) * 4;

    for (int c = 0; c < nCh; c++) {
        if (c + 1 < nCh) { ISSUE2((c + 1) & 1, c + 1); cp_wait1(); }
        else             { cp_wait0(); }
        __syncthreads();

        const uint32_t stb = ab + (uint32_t)(c & 1) * STGB;
        if (full)      { GB_CHUNK(4); }
        else if (half) { GB_CHUNK(2); }
        __syncthreads();
    }

    const int Nw = N >> 1;
    #pragma unroll
    for (int i = 0; i < 4; i++) {
        int r0 = bm + wm * 64 + i * 16 + g;
        int r1 = r0 + 8;
        #pragma unroll
        for (int j = 0; j < 4; j++) {
            int cix = bn + wn * 32 + j * 8 + tig * 2;
            float b0 = bias[cix], b1 = bias[cix + 1];
            float v0 = acc[i][j][0] + b0, v1 = acc[i][j][1] + b1;
            float v2 = acc[i][j][2] + b0, v3 = acc[i][j][3] + b1;
            if (doRelu) {
                v0 = fmaxf(v0, 0.f); v1 = fmaxf(v1, 0.f);
                v2 = fmaxf(v2, 0.f); v3 = fmaxf(v3, 0.f);
            }
            if (C) {
                *(float2*)(C + (size_t)r0 * N + cix) = make_float2(v0, v1);
                *(float2*)(C + (size_t)r1 * N + cix) = make_float2(v2, v3);
            }
            if (Cs_hi) {
                size_t w0 = (size_t)r0 * Nw + (cix >> 1);
                size_t w1 = (size_t)r1 * Nw + (cix >> 1);
                float h0 = __bfloat162float(__float2bfloat16_rn(v0));
                float h1 = __bfloat162float(__float2bfloat16_rn(v1));
                float h2 = __bfloat162float(__float2bfloat16_rn(v2));
                float h3 = __bfloat162float(__float2bfloat16_rn(v3));
                Cs_hi[w0] = pack_bf16(h0, h1);
                Cs_lo[w0] = pack_bf16(v0 - h0, v1 - h1);
                Cs_hi[w1] = pack_bf16(h2, h3);
                Cs_lo[w1] = pack_bf16(v2 - h2, v3 - h3);
            }
        }
    }
}

// -------------------- tensor-core attention (direct V via ldmatrix.trans) ---
#define AT_KH  0
#define AT_KL  18432
#define AT_QH  36864
#define AT_QL  38016
#define AT_PH  39168
#define AT_PL  47488
#define AT_RED 55808
#define AT_WORDS 56320
#define ATTN_SMEM (AT_WORDS * 4)

__global__ __launch_bounds__(256)
void attn_tc(const uint32_t* __restrict__ qh, const uint32_t* __restrict__ ql,
             const uint32_t* __restrict__ kh, const uint32_t* __restrict__ kl,
             const uint32_t* __restrict__ vh, const uint32_t* __restrict__ vl,
             const int* __restrict__ lens, float* __restrict__ O, int rst)
{
    extern __shared__ uint32_t sm[];
    const uint32_t sbase = smem_u32(sm);

    const int qt = blockIdx.x, h = blockIdx.y, b = blockIdx.z;
    const int len  = lens[b];
    if (qt * 32 >= len) return;

    const int tid  = threadIdx.x;
    const int lane = tid & 31;
    const int warp = tid >> 5;
    const int g    = lane >> 2;
    const int tig  = lane & 3;
    const int qbase = b * SS + qt * 32;
    const int nc   = (len + 15) >> 4;
    const int vrows = nc << 4;   // PV consumes rows [0, vrows); all finite in gmem
    const int l15  = lane & 15;
    const int lc4  = (lane >> 4) * 4;
    const int l7   = lane & 7;
    const int lb4  = ((lane >> 3) & 1) * 4;

    {
        int row = tid >> 3, ch = tid & 7;
        cp16(sbase + (uint32_t)(AT_QH + row * 36 + ch * 4) * 4,
             qh + (size_t)(qbase + row) * rst + h * 32 + ch * 4);
        cp16(sbase + (uint32_t)(AT_QL + row * 36 + ch * 4) * 4,
             ql + (size_t)(qbase + row) * rst + h * 32 + ch * 4);
    }
    for (int t = tid; t < 4096; t += 256) {
        int row = t >> 3, ch = t & 7;
        if (row < len) {
            cp16(sbase + (uint32_t)(AT_KH + row * 36 + ch * 4) * 4,
                 kh + (size_t)(b * SS + row) * rst + h * 32 + ch * 4);
            cp16(sbase + (uint32_t)(AT_KL + row * 36 + ch * 4) * 4,
                 kl + (size_t)(b * SS + row) * rst + h * 32 + ch * 4);
        }
    }
    cp_commit(); cp_wait0();
    __syncthreads();

    float acc[2][8][4];
    #pragma unroll
    for (int i = 0; i < 2; i++)
        #pragma unroll
        for (int j = 0; j < 8; j++)
            #pragma unroll
            for (int r = 0; r < 4; r++) acc[i][j][r] = 0.f;

    if (warp * 64 < len) {
        #pragma unroll
        for (int c = 0; c < 4; c++) {
            uint32_t ah[2][4], al[2][4];
            #pragma unroll
            for (int i = 0; i < 2; i++) {
                uint32_t ad = sbase +
                    (uint32_t)(AT_QH + (i * 16 + l15) * 36 + c * 8 + lc4) * 4;
                ldsm4(ah[i], ad);
                ldsm4(al[i], ad + (AT_QL - AT_QH) * 4);
            }
            #pragma unroll
            for (int j = 0; j < 8; j++) {
                uint32_t bd = sbase +
                    (uint32_t)(AT_KH + (warp * 64 + j * 8 + l7) * 36 + c * 8 + lb4) * 4;
                uint32_t bh[2], bl[2];
                ldsm2(bh, bd);
                ldsm2(bl, bd + (AT_KL - AT_KH) * 4);
                #pragma unroll
                for (int i = 0; i < 2; i++) {
                    mma16816(acc[i][j], ah[i], bh);
                    mma16816(acc[i][j], al[i], bh);
                    mma16816(acc[i][j], ah[i], bl);
                }
            }
        }
    }

    const float scale = 0.125f;
    #pragma unroll
    for (int i = 0; i < 2; i++)
        #pragma unroll
        for (int j = 0; j < 8; j++) {
            int c0 = warp * 64 + j * 8 + tig * 2;
            bool m0 = c0 < len, m1 = (c0 + 1) < len;
            acc[i][j][0] = m0 ? acc[i][j][0] * scale : -1e9f;
            acc[i][j][1] = m1 ? acc[i][j][1] * scale : -1e9f;
            acc[i][j][2] = m0 ? acc[i][j][2] * scale : -1e9f;
            acc[i][j][3] = m1 ? acc[i][j][3] * scale : -1e9f;
        }

    float* redM = (float*)(sm + AT_RED);
    float* redS = redM + 256;

    float rmax[2][2];
    #pragma unroll
    for (int i = 0; i < 2; i++)
        #pragma unroll
        for (int sub = 0; sub < 2; sub++) {
            float m = -1e30f;
            #pragma unroll
            for (int j = 0; j < 8; j++) {
                m = fmaxf(m, acc[i][j][2 * sub]);
                m = fmaxf(m, acc[i][j][2 * sub + 1]);
            }
            m = fmaxf(m, __shfl_xor_sync(0xffffffffu, m, 1));
            m = fmaxf(m, __shfl_xor_sync(0xffffffffu, m, 2));
            if (tig == 0) redM[(i * 16 + sub * 8 + g) * 8 + warp] = m;
        }
    __syncthreads();
    #pragma unroll
    for (int i = 0; i < 2; i++)
        #pragma unroll
        for (int sub = 0; sub < 2; sub++) {
            int row = i * 16 + sub * 8 + g;
            float m = -1e30f;
            #pragma unroll
            for (int w = 0; w < 8; w++) m = fmaxf(m, redM[row * 8 + w]);
            rmax[i][sub] = m;
        }

    #pragma unroll
    for (int i = 0; i < 2; i++)
        #pragma unroll
        for (int sub = 0; sub < 2; sub++) {
            float s = 0.f;
            #pragma unroll
            for (int j = 0; j < 8; j++) {
                float e0 = __expf(acc[i][j][2 * sub]     - rmax[i][sub]);
                float e1 = __expf(acc[i][j][2 * sub + 1] - rmax[i][sub]);
                acc[i][j][2 * sub] = e0; acc[i][j][2 * sub + 1] = e1;
                s += e0 + e1;
            }
            s += __shfl_xor_sync(0xffffffffu, s, 1);
            s += __shfl_xor_sync(0xffffffffu, s, 2);
            if (tig == 0) redS[(i * 16 + sub * 8 + g) * 8 + warp] = s;
        }
    __syncthreads();

    #pragma unroll
    for (int i = 0; i < 2; i++)
        #pragma unroll
        for (int sub = 0; sub < 2; sub++) {
            int row = i * 16 + sub * 8 + g;
            float s = 0.f;
            #pragma unroll
            for (int w = 0; w < 8; w++) s += redS[row * 8 + w];
            float inv = 1.f / s;
            #pragma unroll
            for (int j = 0; j < 8; j++) {
                float p0 = acc[i][j][2 * sub] * inv;
                float p1 = acc[i][j][2 * sub + 1] * inv;
                float h0 = __bfloat162float(__float2bfloat16_rn(p0));
                float h1 = __bfloat162float(__float2bfloat16_rn(p1));
                int wi = row * 260 + warp * 32 + j * 4 + tig;
                sm[AT_PH + wi] = pack_bf16(h0, h1);
                sm[AT_PL + wi] = pack_bf16(p0 - h0, p1 - h1);
            }
        }
    __syncthreads();

    // load V (row-major [s][d], same layout as K) over the K region.
    // rows < vrows (= 16*nc): PV tail reads [len, vrows) multiplied by P==0,
    // and gmem there is finite — avoids uninitialized-smem NaN poisoning.
    for (int t = tid; t < 4096; t += 256) {
        int row = t >> 3, ch = t & 7;
        if (row < vrows) {
            cp16(sbase + (uint32_t)(AT_KH + row * 36 + ch * 4) * 4,
                 vh + (size_t)(b * SS + row) * rst + h * 32 + ch * 4);
            cp16(sbase + (uint32_t)(AT_KL + row * 36 + ch * 4) * 4,
                 vl + (size_t)(b * SS + row) * rst + h * 32 + ch * 4);
        }
    }
    cp_commit(); cp_wait0();
    __syncthreads();

    // PV: B fragments via ldmatrix.x2.trans on V[s][d]
    const int wm2 = warp >> 2, wn2 = warp & 3;
    float oacc[2][4];
    #pragma unroll
    for (int j = 0; j < 2; j++)
        #pragma unroll
        for (int r = 0; r < 4; r++) oacc[j][r] = 0.f;

    #pragma unroll 4
    for (int c = 0; c < nc; c++) {
        uint32_t ah[4], al[4];
        uint32_t ad = sbase +
            (uint32_t)(AT_PH + (wm2 * 16 + l15) * 260 + c * 8 + lc4) * 4;
        ldsm4(ah, ad);
        ldsm4(al, ad + (AT_PL - AT_PH) * 4);
        #pragma unroll
        for (int j = 0; j < 2; j++) {
            uint32_t vd = sbase + (uint32_t)(AT_KH + (c * 16 + l15) * 36) * 4
                        + (uint32_t)(wn2 * 16 + j * 8) * 2;
            uint32_t bh[2], bl[2];
            ldsm2t(bh, vd);
            ldsm2t(bl, vd + (AT_KL - AT_KH) * 4);
            mma16816(oacc[j], ah, bh);
            mma16816(oacc[j], al, bh);
            mma16816(oacc[j], ah, bl);
        }
    }

    #pragma unroll
    for (int j = 0; j < 2; j++) {
        int col = h * DHD + wn2 * 16 + j * 8 + tig * 2;
        int r0 = qbase + wm2 * 16 + g;
        int r1 = r0 + 8;
        *(float2*)(O + (size_t)r0 * DD + col) = make_float2(oacc[j][0], oacc[j][1]);
        *(float2*)(O + (size_t)r1 * DD + col) = make_float2(oacc[j][2], oacc[j][3]);
    }
}

// -------------------- fused residual + LayerNorm + split (one-pass) ---------
__global__ __launch_bounds__(192)
void add_ln(const float* __restrict__ x, const float* __restrict__ y,
            const float* __restrict__ g, const float* __restrict__ bt,
            float* __restrict__ out, uint32_t* __restrict__ s_hi,
            uint32_t* __restrict__ s_lo, const int* __restrict__ lens)
{
    const int row = blockIdx.x;
    if ((row & (SS - 1)) >= lens[row >> 9]) return;
    const int tid = threadIdx.x;
    const int c0 = tid * 4;
    float4 xv = *(const float4*)(x + (size_t)row * DD + c0);
    float4 yv = *(const float4*)(y + (size_t)row * DD + c0);
    float v0 = xv.x + yv.x, v1 = xv.y + yv.y, v2 = xv.z + yv.z, v3 = xv.w + yv.w;
    float s  = v0 + v1 + v2 + v3;
    float sq = v0 * v0 + v1 * v1 + v2 * v2 + v3 * v3;
    blockReduceSum2(s, sq);
    float mean = s * (1.0f / DD);
    float var  = sq * (1.0f / DD) - mean * mean;
    float rstd = rsqrtf(var + 1e-5f);
    float d0 = v0 - mean, d1 = v1 - mean, d2 = v2 - mean, d3 = v3 - mean;
    float4 gv = *(const float4*)(g + c0);
    float4 bv = *(const float4*)(bt + c0);
    float o0 = d0 * rstd * gv.x + bv.x;
    float o1 = d1 * rstd * gv.y + bv.y;
    float o2 = d2 * rstd * gv.z + bv.z;
    float o3 = d3 * rstd * gv.w + bv.w;
    *(float4*)(out + (size_t)row * DD + c0) = make_float4(o0, o1, o2, o3);
    float h0 = __bfloat162float(__float2bfloat16_rn(o0));
    float h1 = __bfloat162float(__float2bfloat16_rn(o1));
    float h2 = __bfloat162float(__float2bfloat16_rn(o2));
    float h3 = __bfloat162float(__float2bfloat16_rn(o3));
    size_t w = (size_t)row * (DD / 2) + tid * 2;
    s_hi[w]     = pack_bf16(h0, h1);
    s_lo[w]     = pack_bf16(o0 - h0, o1 - h1);
    s_hi[w + 1] = pack_bf16(h2, h3);
    s_lo[w + 1] = pack_bf16(o2 - h2, o3 - h3);
}

// -------------------- masked mean pool + output projection -------------------
__global__ __launch_bounds__(256)
void pool_out(const float* __restrict__ hbuf, const int* __restrict__ lens,
              const float* __restrict__ ow, const float* __restrict__ ob,
              float* __restrict__ out)
{
    __shared__ float ps[8][DD];
    const int b = blockIdx.x;
    const int tid = threadIdx.x;
    const int warp = tid >> 5, lane = tid & 31;
    const int len = lens[b];
    float r[24];
    #pragma unroll
    for (int i = 0; i < 24; i++) r[i] = 0.f;
    for (int sp = warp; sp < len; sp += 8) {
        const float* row = hbuf + (size_t)(b * SS + sp) * DD;
        #pragma unroll
        for (int i = 0; i < 24; i++) r[i] += row[i * 32 + lane];
    }
    #pragma unroll
    for (int i = 0; i < 24; i++) ps[warp][i * 32 + lane] = r[i];
    __syncthreads();
    const float inv = 1.0f / (float)len;
    float acc = 0.f;
    #pragma unroll
    for (int i = 0; i < 3; i++) {
        int d = tid + i * 256;
        float s = 0.f;
        #pragma unroll
        for (int w = 0; w < 8; w++) s += ps[w][d];
        acc += s * inv * ow[d];
    }
    float tot = blockReduceSum(acc);
    if (tid == 0) out[b] = tot + ob[0];
}

// -------------------- launcher --------------------
extern "C" void kernel_launch(void* const* d_in, const int* in_sizes, int n_in,
                              void* d_out, int out_size)
{
    const float* x    = (const float*)d_in[0];
    const int*   lens = (const int*)  d_in[1];
    const float* in_w = (const float*)d_in[2];
    const float* in_b = (const float*)d_in[3];
    const float* pos  = (const float*)d_in[4];
    const float* qw   = (const float*)d_in[5];
    const float* qb   = (const float*)d_in[6];
    const float* kw   = (const float*)d_in[7];
    const float* kb   = (const float*)d_in[8];
    const float* vw   = (const float*)d_in[9];
    const float* vb   = (const float*)d_in[10];
    const float* w1   = (const float*)d_in[11];
    const float* b1   = (const float*)d_in[12];
    const float* w2   = (const float*)d_in[13];
    const float* b2   = (const float*)d_in[14];
    const float* ln1g = (const float*)d_in[15];
    const float* ln1b = (const float*)d_in[16];
    const float* ln2g = (const float*)d_in[17];
    const float* ln2b = (const float*)d_in[18];
    const float* ow   = (const float*)d_in[19];
    const float* ob   = (const float*)d_in[20];
    float* out = (float*)d_out;

    float *h, *o, *qkvb;
    uint32_t *xs_hi, *xs_lo, *hs_hi, *hs_lo, *ff_hi, *ff_lo, *w_hi, *w_lo;
    uint32_t *qkv_hi, *qkv_lo;
    cudaGetSymbolAddress((void**)&h,  g_h);
    cudaGetSymbolAddress((void**)&o,  g_o);
    cudaGetSymbolAddress((void**)&qkvb, g_qkvb);
    cudaGetSymbolAddress((void**)&xs_hi, g_xs_hi);
    cudaGetSymbolAddress((void**)&xs_lo, g_xs_lo);
    cudaGetSymbolAddress((void**)&hs_hi, g_hs_hi);
    cudaGetSymbolAddress((void**)&hs_lo, g_hs_lo);
    cudaGetSymbolAddress((void**)&ff_hi, g_ff_hi);
    cudaGetSymbolAddress((void**)&ff_lo, g_ff_lo);
    cudaGetSymbolAddress((void**)&qkv_hi, g_qkv_hi);
    cudaGetSymbolAddress((void**)&qkv_lo, g_qkv_lo);
    cudaGetSymbolAddress((void**)&w_hi,  g_w_hi);
    cudaGetSymbolAddress((void**)&w_lo,  g_w_lo);

    cudaFuncSetAttribute(gemm_tc, cudaFuncAttributeMaxDynamicSharedMemorySize,
                         GEMM_SMEM);
    cudaFuncSetAttribute(gemm_big, cudaFuncAttributeMaxDynamicSharedMemorySize,
                         GB_SMEM);
    cudaFuncSetAttribute(attn_tc, cudaFuncAttributeMaxDynamicSharedMemorySize,
                         ATTN_SMEM);

    const long QKV_L = 3L * DD * DD / 2;
    const long FFN_L = (long)DD * DFF_ / 2;

    const dim3 gD(DD / 128, MROWS / 128);
    const dim3 gQKV(3 * DD / 128, MROWS / 128);
    const dim3 gF(DFF_ / 128, MROWS / 128);
    const dim3 gA(SS / 32, HH, BB);

    xsplit<<<(MROWS * INF_ / 2 + 255) / 256, 256>>>(x, xs_hi, xs_lo, MROWS * INF_ / 2);
    wsplit<<<dim3(DD/64, 1, 1), 256>>>(in_w, w_hi + W_INW, w_lo + W_INW,
                                       INF_, DD, 12288);
    gemm_tc<<<gD, 256, GEMM_SMEM>>>(xs_hi, xs_lo, w_hi + W_INW, w_lo + W_INW,
                                    in_b, pos, h, hs_hi, hs_lo, DD, INF_, 0, lens);
    catb<<<(LL * 3 * DD + 255) / 256, 256>>>(qb, kb, vb, qkvb);
    wsplit3<<<dim3(DD/64, DD/64, 3*LL), 256>>>(qw, kw, vw, w_hi + W_QKV, w_lo + W_QKV);

    for (int l = 0; l < LL; l++) {
        const size_t woQ = (size_t)l * QKV_L;
        const size_t woF = (size_t)l * FFN_L;
        const size_t bo  = (size_t)l * DD;
        gemm_big<<<gQKV, 256, GB_SMEM>>>(hs_hi, hs_lo,
                                         w_hi + W_QKV + woQ, w_lo + W_QKV + woQ,
                                         qkvb + (size_t)l * 3 * DD, nullptr,
                                         qkv_hi, qkv_lo, 3 * DD, DD, 0, lens);
        if (l == 0) {
            wsplit<<<dim3(DFF_/64, DD/64, LL), 256>>>(w1, w_hi + W_W1, w_lo + W_W1,
                                                      DD, DFF_, FFN_L);
            wsplit<<<dim3(DD/64, DFF_/64, LL), 256>>>(w2, w_hi + W_W2, w_lo + W_W2,
                                                      DFF_, DD, FFN_L);
        }
        attn_tc<<<gA, 256, ATTN_SMEM>>>(qkv_hi, qkv_lo,
                                        qkv_hi + (DD / 2), qkv_lo + (DD / 2),
                                        qkv_hi + 2 * (DD / 2), qkv_lo + 2 * (DD / 2),
                                        lens, o, 3 * DD / 2);
        add_ln<<<MROWS, 192>>>(h, o, ln1g + bo, ln1b + bo, h, hs_hi, hs_lo, lens);
        gemm_big<<<gF, 256, GB_SMEM>>>(hs_hi, hs_lo,
                                       w_hi + W_W1 + woF, w_lo + W_W1 + woF,
                                       b1 + (size_t)l * DFF_, nullptr,
                                       ff_hi, ff_lo, DFF_, DD, 1, lens);
        gemm_big<<<gD, 256, GB_SMEM>>>(ff_hi, ff_lo,
                                       w_hi + W_W2 + woF, w_lo + W_W2 + woF,
                                       b2 + bo, o, nullptr, nullptr, DD, DFF_, 0, lens);
        add_ln<<<MROWS, 192>>>(h, o, ln2g + bo, ln2b + bo, h, hs_hi, hs_lo, lens);
    }

    pool_out<<<BB, 256>>>(h, lens, ow, ob, out);
}

// round 17
// speedup vs baseline: 1.2077x; 1.0116x over previous
#include <cuda_runtime.h>
#include <cuda_bf16.h>
#include <math.h>
#include <stdint.h>

// Problem constants
#define BB   16
#define SS   512
#define INF_ 32
#define DD   768
#define HH   12
#define LL   6
#define DHD  64
#define DFF_ 3072
#define MROWS (BB*SS)   // 8192

// -------------------- device scratch --------------------
__device__ float g_h [MROWS*DD];
__device__ float g_o [MROWS*DD];

__device__ uint32_t g_xs_hi[MROWS*INF_/2],  g_xs_lo[MROWS*INF_/2];
__device__ uint32_t g_hs_hi[MROWS*DD/2],    g_hs_lo[MROWS*DD/2];
__device__ uint32_t g_ff_hi[MROWS*DFF_/2],  g_ff_lo[MROWS*DFF_/2];
__device__ uint32_t g_qkv_hi[MROWS*3*DD/2], g_qkv_lo[MROWS*3*DD/2];
__device__ float    g_qkvb[LL*3*DD];

// split + transposed weights ([N][K/2] words per tensor)
#define W_INW 0
#define W_QKV 12288                       // L x [2304][384], layer stride 884736
#define W_W1  5320704                     // L x [3072][384], layer stride 1179648
#define W_W2  12398592                    // L x [768][1536], layer stride 1179648
#define W_TOT 19476480
__device__ uint32_t g_w_hi[W_TOT];
__device__ uint32_t g_w_lo[W_TOT];

// -------------------- helpers --------------------
__device__ __forceinline__ uint32_t pack_bf16(float x, float y) {
    __nv_bfloat162 t = __floats2bfloat162_rn(x, y);
    return *reinterpret_cast<uint32_t*>(&t);
}

__device__ __forceinline__ float blockReduceSum(float val) {
    __shared__ float sh[8];
    __syncthreads();
    int lane = threadIdx.x & 31, warp = threadIdx.x >> 5;
    int nw = blockDim.x >> 5;
    #pragma unroll
    for (int o = 16; o; o >>= 1) val += __shfl_xor_sync(0xffffffffu, val, o);
    if (lane == 0) sh[warp] = val;
    __syncthreads();
    if (warp == 0) {
        float v = (lane < nw) ? sh[lane] : 0.f;
        #pragma unroll
        for (int o = 4; o; o >>= 1) v += __shfl_xor_sync(0xffffffffu, v, o);
        if (lane == 0) sh[0] = v;
    }
    __syncthreads();
    return sh[0];
}

// fused 2-value block reduce (single barrier round); call once per kernel
__device__ __forceinline__ void blockReduceSum2(float& a, float& b) {
    __shared__ float sh[16];
    int lane = threadIdx.x & 31, warp = threadIdx.x >> 5;
    int nw = blockDim.x >> 5;
    #pragma unroll
    for (int o = 16; o; o >>= 1) {
        a += __shfl_xor_sync(0xffffffffu, a, o);
        b += __shfl_xor_sync(0xffffffffu, b, o);
    }
    if (lane == 0) { sh[warp] = a; sh[warp + 8] = b; }
    __syncthreads();
    if (warp == 0) {
        float va = (lane < nw) ? sh[lane] : 0.f;
        float vb = (lane < nw) ? sh[lane + 8] : 0.f;
        #pragma unroll
        for (int o = 4; o; o >>= 1) {
            va += __shfl_xor_sync(0xffffffffu, va, o);
            vb += __shfl_xor_sync(0xffffffffu, vb, o);
        }
        if (lane == 0) { sh[0] = va; sh[8] = vb; }
    }
    __syncthreads();
    a = sh[0]; b = sh[8];
}

__device__ __forceinline__ void mma16816(float* d, const uint32_t* a, const uint32_t* b) {
    asm volatile(
        "mma.sync.aligned.m16n8k16.row.col.f32.bf16.bf16.f32 "
        "{%0,%1,%2,%3}, {%4,%5,%6,%7}, {%8,%9}, {%0,%1,%2,%3};\n"
        : "+f"(d[0]), "+f"(d[1]), "+f"(d[2]), "+f"(d[3])
        : "r"(a[0]), "r"(a[1]), "r"(a[2]), "r"(a[3]), "r"(b[0]), "r"(b[1]));
}

__device__ __forceinline__ void ldsm4(uint32_t* r, uint32_t addr) {
    asm volatile("ldmatrix.sync.aligned.m8n8.x4.shared.b16 {%0,%1,%2,%3}, [%4];"
                 : "=r"(r[0]), "=r"(r[1]), "=r"(r[2]), "=r"(r[3]) : "r"(addr));
}
__device__ __forceinline__ void ldsm2(uint32_t* r, uint32_t addr) {
    asm volatile("ldmatrix.sync.aligned.m8n8.x2.shared.b16 {%0,%1}, [%2];"
                 : "=r"(r[0]), "=r"(r[1]) : "r"(addr));
}
__device__ __forceinline__ void ldsm2t(uint32_t* r, uint32_t addr) {
    asm volatile("ldmatrix.sync.aligned.m8n8.x2.trans.shared.b16 {%0,%1}, [%2];"
                 : "=r"(r[0]), "=r"(r[1]) : "r"(addr));
}

__device__ __forceinline__ void cp16(uint32_t dst, const void* src) {
    asm volatile("cp.async.cg.shared.global [%0], [%1], 16;\n" :: "r"(dst), "l"(src));
}
__device__ __forceinline__ void cp_commit() { asm volatile("cp.async.commit_group;\n"); }
__device__ __forceinline__ void cp_wait0()  { asm volatile("cp.async.wait_group 0;\n"); }
__device__ __forceinline__ void cp_wait1()  { asm volatile("cp.async.wait_group 1;\n"); }

__device__ __forceinline__ uint32_t smem_u32(const void* p) {
    return (uint32_t)__cvta_generic_to_shared(p);
}

// -------------------- weight transpose + split (vectorized) -----------------
__device__ __forceinline__ void wsplit_body(
    const float* __restrict__ W, uint32_t* __restrict__ hi,
    uint32_t* __restrict__ lo, int K, int N, int n0, int k0, int tid,
    float (*t)[65])
{
    #pragma unroll
    for (int i = 0; i < 4; i++) {
        int idx = tid + i * 256;
        int k = idx >> 4, f = (idx & 15) * 4;
        if (k0 + k < K) {
            float4 v = *(const float4*)(W + (size_t)(k0 + k) * N + n0 + f);
            t[k][f] = v.x; t[k][f + 1] = v.y; t[k][f + 2] = v.z; t[k][f + 3] = v.w;
        }
    }
    __syncthreads();
    const int Kw = K >> 1;
    #pragma unroll
    for (int i = 0; i < 2; i++) {
        int idx = tid + i * 256;
        int n = idx >> 3, wq = idx & 7;
        if (k0 / 2 + wq * 4 < Kw) {
            uint32_t hh[4], ll[4];
            #pragma unroll
            for (int j = 0; j < 4; j++) {
                int kk = wq * 8 + j * 2;
                float a = t[kk][n], b = t[kk + 1][n];
                float ha = __bfloat162float(__float2bfloat16_rn(a));
                float hb = __bfloat162float(__float2bfloat16_rn(b));
                hh[j] = pack_bf16(ha, hb);
                ll[j] = pack_bf16(a - ha, b - hb);
            }
            size_t wi = (size_t)(n0 + n) * Kw + k0 / 2 + wq * 4;
            *(uint4*)(hi + wi) = make_uint4(hh[0], hh[1], hh[2], hh[3]);
            *(uint4*)(lo + wi) = make_uint4(ll[0], ll[1], ll[2], ll[3]);
        }
    }
}

__global__ __launch_bounds__(256)
void wsplit(const float* __restrict__ W, uint32_t* __restrict__ hi,
            uint32_t* __restrict__ lo, int K, int N, long lstr)
{
    __shared__ float t[64][65];
    const int l = blockIdx.z;
    wsplit_body(W + (size_t)l * K * N, hi + (size_t)l * lstr,
                lo + (size_t)l * lstr, K, N,
                blockIdx.x * 64, blockIdx.y * 64, threadIdx.x, t);
}

__global__ __launch_bounds__(256)
void wsplit3(const float* __restrict__ q, const float* __restrict__ k,
             const float* __restrict__ v, uint32_t* __restrict__ hi,
             uint32_t* __restrict__ lo)
{
    __shared__ float t[64][65];
    const int z = blockIdx.z, l = z / 3, t3 = z % 3;
    const float* W = (t3 == 0 ? q : (t3 == 1 ? k : v)) + (size_t)l * DD * DD;
    const size_t off = (size_t)l * (3L * DD * DD / 2) + (size_t)t3 * (DD * DD / 2);
    wsplit_body(W, hi + off, lo + off, DD, DD,
                blockIdx.x * 64, blockIdx.y * 64, threadIdx.x, t);
}

__global__ void xsplit(const float* __restrict__ src, uint32_t* __restrict__ hi,
                       uint32_t* __restrict__ lo, int nPairs)
{
    int i = blockIdx.x * blockDim.x + threadIdx.x;
    if (i < nPairs) {
        float2 v = *(const float2*)(src + 2 * i);
        float h0 = __bfloat162float(__float2bfloat16_rn(v.x));
        float h1 = __bfloat162float(__float2bfloat16_rn(v.y));
        hi[i] = pack_bf16(h0, h1);
        lo[i] = pack_bf16(v.x - h0, v.y - h1);
    }
}

__global__ void catb(const float* __restrict__ qb, const float* __restrict__ kb,
                     const float* __restrict__ vb, float* __restrict__ o)
{
    int idx = blockIdx.x * 256 + threadIdx.x;
    if (idx < LL * 3 * DD) {
        int l = idx / (3 * DD), r = idx % (3 * DD);
        float v = (r < DD) ? qb[l * DD + r]
                : (r < 2 * DD) ? kb[l * DD + r - DD] : vb[l * DD + r - 2 * DD];
        o[idx] = v;
    }
}

// -------------------- legacy bf16x2 GEMM (K=32 in-proj only) ----------------
#define RS 20
#define STG 10240
#define GEMM_SMEM (2 * STG * 4)

__global__ __launch_bounds__(256)
void gemm_tc(const uint32_t* __restrict__ A_hi, const uint32_t* __restrict__ A_lo,
             const uint32_t* __restrict__ W_hi, const uint32_t* __restrict__ W_lo,
             const float* __restrict__ bias, const float* __restrict__ pos,
             float* __restrict__ C, uint32_t* __restrict__ Cs_hi,
             uint32_t* __restrict__ Cs_lo, int N, int K, int doRelu,
             const int* __restrict__ lens)
{
    extern __shared__ uint32_t sm[];
    const uint32_t sbase = smem_u32(sm);

    const int bm   = blockIdx.y * 128;
    if ((bm & (SS - 1)) >= lens[bm >> 9]) return;

    const int tid  = threadIdx.x;
    const int lane = tid & 31;
    const int warp = tid >> 5;
    const int g    = lane >> 2;
    const int tig  = lane & 3;
    const int wm   = warp >> 2;
    const int wn   = warp & 3;
    const int bn   = blockIdx.x * 128;
    const int Kw   = K >> 1;

    const int cr = tid >> 2;
    const int cc = (tid & 3) << 2;

    float acc[4][4][4];
    #pragma unroll
    for (int i = 0; i < 4; i++)
        #pragma unroll
        for (int j = 0; j < 4; j++)
            #pragma unroll
            for (int r = 0; r < 4; r++) acc[i][j][r] = 0.f;

    const int nChunks = K >> 5;

    const uint32_t* srcA_hi = A_hi + (size_t)(bm + cr) * Kw + cc;
    const uint32_t* srcA_lo = A_lo + (size_t)(bm + cr) * Kw + cc;
    const uint32_t* srcB_hi = W_hi + (size_t)(bn + cr) * Kw + cc;
    const uint32_t* srcB_lo = W_lo + (size_t)(bn + cr) * Kw + cc;
    const size_t rstep = (size_t)64 * Kw;

    #define ISSUE(stage, c) do {                                               \
        uint32_t db = sbase + (uint32_t)((stage) * STG) * 4;                   \
        int kw0 = (c) * 16;                                                    \
        uint32_t d0 = db + (uint32_t)(cr * RS + cc) * 4;                       \
        uint32_t d1 = db + (uint32_t)((cr + 64) * RS + cc) * 4;                \
        cp16(d0,              srcA_hi + kw0);                                  \
        cp16(d1,              srcA_hi + kw0 + rstep);                          \
        cp16(d0 + 2560 * 4,   srcA_lo + kw0);                                  \
        cp16(d1 + 2560 * 4,   srcA_lo + kw0 + rstep);                          \
        cp16(d0 + 5120 * 4,   srcB_hi + kw0);                                  \
        cp16(d1 + 5120 * 4,   srcB_hi + kw0 + rstep);                          \
        cp16(d0 + 7680 * 4,   srcB_lo + kw0);                                  \
        cp16(d1 + 7680 * 4,   srcB_lo + kw0 + rstep);                          \
        cp_commit();                                                           \
    } while (0)

    ISSUE(0, 0);

    for (int c = 0; c < nChunks; c++) {
        if (c + 1 < nChunks) { ISSUE((c + 1) & 1, c + 1); cp_wait1(); }
        else                 { cp_wait0(); }
        __syncthreads();

        const uint32_t* S   = sm + (c & 1) * STG;
        const uint32_t* sAh = S;
        const uint32_t* sAl = S + 2560;
        const uint32_t* sBh = S + 5120;
        const uint32_t* sBl = S + 7680;

        #pragma unroll
        for (int h = 0; h < 2; h++) {
            const int cA = h * 8 + tig;
            uint32_t ah[4][4], al[4][4], bh[4][2], bl[4][2];
            #pragma unroll
            for (int i = 0; i < 4; i++) {
                int m = (wm * 64 + i * 16 + g) * RS + cA;
                ah[i][0] = sAh[m];               ah[i][1] = sAh[m + 8 * RS];
                ah[i][2] = sAh[m + 4];           ah[i][3] = sAh[m + 8 * RS + 4];
                al[i][0] = sAl[m];               al[i][1] = sAl[m + 8 * RS];
                al[i][2] = sAl[m + 4];           al[i][3] = sAl[m + 8 * RS + 4];
            }
            #pragma unroll
            for (int j = 0; j < 4; j++) {
                int n = (wn * 32 + j * 8 + g) * RS + cA;
                bh[j][0] = sBh[n];  bh[j][1] = sBh[n + 4];
                bl[j][0] = sBl[n];  bl[j][1] = sBl[n + 4];
            }
            #pragma unroll
            for (int j = 0; j < 4; j++)
                #pragma unroll
                for (int i = 0; i < 4; i++) {
                    mma16816(acc[i][j], ah[i], bh[j]);
                    mma16816(acc[i][j], al[i], bh[j]);
                    mma16816(acc[i][j], ah[i], bl[j]);
                }
        }
        __syncthreads();
    }

    const int Nw = N >> 1;
    #pragma unroll
    for (int i = 0; i < 4; i++) {
        int r0 = bm + wm * 64 + i * 16 + g;
        int r1 = r0 + 8;
        #pragma unroll
        for (int j = 0; j < 4; j++) {
            int cix = bn + wn * 32 + j * 8 + tig * 2;
            float b0 = bias[cix], b1 = bias[cix + 1];
            float v0 = acc[i][j][0] + b0, v1 = acc[i][j][1] + b1;
            float v2 = acc[i][j][2] + b0, v3 = acc[i][j][3] + b1;
            if (pos) {
                int s0 = r0 & (SS - 1), s1 = r1 & (SS - 1);
                v0 += pos[(size_t)s0 * N + cix];
                v1 += pos[(size_t)s0 * N + cix + 1];
                v2 += pos[(size_t)s1 * N + cix];
                v3 += pos[(size_t)s1 * N + cix + 1];
            }
            if (doRelu) {
                v0 = fmaxf(v0, 0.f); v1 = fmaxf(v1, 0.f);
                v2 = fmaxf(v2, 0.f); v3 = fmaxf(v3, 0.f);
            }
            if (C) {
                *(float2*)(C + (size_t)r0 * N + cix) = make_float2(v0, v1);
                *(float2*)(C + (size_t)r1 * N + cix) = make_float2(v2, v3);
            }
            if (Cs_hi) {
                size_t w0 = (size_t)r0 * Nw + (cix >> 1);
                size_t w1 = (size_t)r1 * Nw + (cix >> 1);
                float h0 = __bfloat162float(__float2bfloat16_rn(v0));
                float h1 = __bfloat162float(__float2bfloat16_rn(v1));
                float h2 = __bfloat162float(__float2bfloat16_rn(v2));
                float h3 = __bfloat162float(__float2bfloat16_rn(v3));
                Cs_hi[w0] = pack_bf16(h0, h1);
                Cs_lo[w0] = pack_bf16(v0 - h0, v1 - h1);
                Cs_hi[w1] = pack_bf16(h2, h3);
                Cs_lo[w1] = pack_bf16(v2 - h2, v3 - h3);
            }
        }
    }
}

// -------------------- big GEMM: BK=64, ldmatrix, four-path dead-skip --------
#define BRS  36
#define ARRB (128 * BRS * 4)    // 18432 B per array
#define STGB (4 * ARRB)         // 73728 B per stage
#define GB_SMEM (2 * STGB)      // 147456 B

// unconditional chunk body over NI i-tiles (NI compile-time: 1..4)
#define GB_CHUNK(NI) do {                                                      \
    _Pragma("unroll")                                                          \
    for (int h = 0; h < 4; h++) {                                              \
        uint32_t ah[NI][4], al[NI][4], bh[4][2], bl[4][2];                     \
        _Pragma("unroll")                                                      \
        for (int i = 0; i < NI; i++) {                                         \
            uint32_t ad = stb +                                                \
                (uint32_t)((wm * 64 + i * 16 + l15) * BRS + h * 8 + lc4) * 4;  \
            ldsm4(ah[i], ad);                                                  \
            ldsm4(al[i], ad + ARRB);                                           \
        }                                                                      \
        _Pragma("unroll")                                                      \
        for (int j = 0; j < 4; j++) {                                          \
            uint32_t bd = stb + 2u * ARRB +                                    \
                (uint32_t)((wn * 32 + j * 8 + l7) * BRS + h * 8 + lb4) * 4;    \
            ldsm2(bh[j], bd);                                                  \
            ldsm2(bl[j], bd + ARRB);                                           \
        }                                                                      \
        _Pragma("unroll")                                                      \
        for (int j = 0; j < 4; j++)                                            \
            _Pragma("unroll")                                                  \
            for (int i = 0; i < NI; i++) {                                     \
                mma16816(acc[i][j], ah[i], bh[j]);                             \
                mma16816(acc[i][j], al[i], bh[j]);                             \
                mma16816(acc[i][j], ah[i], bl[j]);                             \
            }                                                                  \
    }                                                                          \
} while (0)

__global__ __launch_bounds__(256)
void gemm_big(const uint32_t* __restrict__ A_hi, const uint32_t* __restrict__ A_lo,
              const uint32_t* __restrict__ W_hi, const uint32_t* __restrict__ W_lo,
              const float* __restrict__ bias, float* __restrict__ C,
              uint32_t* __restrict__ Cs_hi, uint32_t* __restrict__ Cs_lo,
              int N, int K, int doRelu, const int* __restrict__ lens)
{
    extern __shared__ uint32_t sm[];
    const uint32_t ab = smem_u32(sm);

    const int bm   = blockIdx.y * 128;
    const int mlen = lens[bm >> 9] - (bm & (SS - 1));  // rows alive in this tile
    if (mlen <= 0) return;

    const int tid  = threadIdx.x;
    const int lane = tid & 31;
    const int warp = tid >> 5;
    const int g    = lane >> 2;
    const int tig  = lane & 3;
    const int wm   = warp >> 2;
    const int wn   = warp & 3;
    const int bn   = blockIdx.x * 128;
    const int Kw   = K >> 1;
    const int nCh  = K >> 6;
    const int mrem = mlen - wm * 64;       // live rows in this warp's half

    float acc[4][4][4];
    #pragma unroll
    for (int i = 0; i < 4; i++)
        #pragma unroll
        for (int j = 0; j < 4; j++)
            #pragma unroll
            for (int r = 0; r < 4; r++) acc[i][j][r] = 0.f;

    #define ISSUE2(stage, c) do {                                              \
        const uint32_t sb = ab + (uint32_t)(stage) * STGB;                     \
        _Pragma("unroll")                                                      \
        for (int t = 0; t < 16; t++) {                                         \
            int idx = tid + t * 256;                                           \
            int arr = idx >> 10;                                               \
            int rem = idx & 1023;                                              \
            int r   = rem >> 3;                                                \
            int u   = rem & 7;                                                 \
            const uint32_t* base = (arr == 0) ? A_hi : (arr == 1) ? A_lo       \
                                 : (arr == 2) ? W_hi : W_lo;                   \
            int row = ((arr < 2) ? bm : bn) + r;                               \
            cp16(sb + (uint32_t)arr * ARRB + (uint32_t)(r * BRS + u * 4) * 4,  \
                 base + (size_t)row * Kw + (c) * 32 + u * 4);                  \
        }                                                                      \
        cp_commit();                                                           \
    } while (0)

    ISSUE2(0, 0);

    const int l15 = lane & 15;
    const int lc4 = (lane >> 4) * 4;
    const int l7  = lane & 7;
    const int lb4 = ((lane >> 3) & 1) * 4;

    for (int c = 0; c < nCh; c++) {
        if (c + 1 < nCh) { ISSUE2((c + 1) & 1, c + 1); cp_wait1(); }
        else             { cp_wait0(); }
        __syncthreads();

        const uint32_t stb = ab + (uint32_t)(c & 1) * STGB;
        if      (mrem > 48) { GB_CHUNK(4); }
        else if (mrem > 32) { GB_CHUNK(3); }
        else if (mrem > 16) { GB_CHUNK(2); }
        else if (mrem > 0)  { GB_CHUNK(1); }
        __syncthreads();
    }

    const int Nw = N >> 1;
    #pragma unroll
    for (int i = 0; i < 4; i++) {
        int r0 = bm + wm * 64 + i * 16 + g;
        int r1 = r0 + 8;
        #pragma unroll
        for (int j = 0; j < 4; j++) {
            int cix = bn + wn * 32 + j * 8 + tig * 2;
            float b0 = bias[cix], b1 = bias[cix + 1];
            float v0 = acc[i][j][0] + b0, v1 = acc[i][j][1] + b1;
            float v2 = acc[i][j][2] + b0, v3 = acc[i][j][3] + b1;
            if (doRelu) {
                v0 = fmaxf(v0, 0.f); v1 = fmaxf(v1, 0.f);
                v2 = fmaxf(v2, 0.f); v3 = fmaxf(v3, 0.f);
            }
            if (C) {
                *(float2*)(C + (size_t)r0 * N + cix) = make_float2(v0, v1);
                *(float2*)(C + (size_t)r1 * N + cix) = make_float2(v2, v3);
            }
            if (Cs_hi) {
                size_t w0 = (size_t)r0 * Nw + (cix >> 1);
                size_t w1 = (size_t)r1 * Nw + (cix >> 1);
                float h0 = __bfloat162float(__float2bfloat16_rn(v0));
                float h1 = __bfloat162float(__float2bfloat16_rn(v1));
                float h2 = __bfloat162float(__float2bfloat16_rn(v2));
                float h3 = __bfloat162float(__float2bfloat16_rn(v3));
                Cs_hi[w0] = pack_bf16(h0, h1);
                Cs_lo[w0] = pack_bf16(v0 - h0, v1 - h1);
                Cs_hi[w1] = pack_bf16(h2, h3);
                Cs_lo[w1] = pack_bf16(v2 - h2, v3 - h3);
            }
        }
    }
}

// -------------------- tensor-core attention (direct V via ldmatrix.trans) ---
#define AT_KH  0
#define AT_KL  18432
#define AT_QH  36864
#define AT_QL  38016
#define AT_PH  39168
#define AT_PL  47488
#define AT_RED 55808
#define AT_WORDS 56320
#define ATTN_SMEM (AT_WORDS * 4)

__global__ __launch_bounds__(256)
void attn_tc(const uint32_t* __restrict__ qh, const uint32_t* __restrict__ ql,
             const uint32_t* __restrict__ kh, const uint32_t* __restrict__ kl,
             const uint32_t* __restrict__ vh, const uint32_t* __restrict__ vl,
             const int* __restrict__ lens, float* __restrict__ O, int rst)
{
    extern __shared__ uint32_t sm[];
    const uint32_t sbase = smem_u32(sm);

    const int qt = blockIdx.x, h = blockIdx.y, b = blockIdx.z;
    const int len  = lens[b];
    if (qt * 32 >= len) return;

    const int tid  = threadIdx.x;
    const int lane = tid & 31;
    const int warp = tid >> 5;
    const int g    = lane >> 2;
    const int tig  = lane & 3;
    const int qbase = b * SS + qt * 32;
    const int nc   = (len + 15) >> 4;
    const int vrows = nc << 4;   // PV consumes rows [0, vrows); all finite in gmem
    const int l15  = lane & 15;
    const int lc4  = (lane >> 4) * 4;
    const int l7   = lane & 7;
    const int lb4  = ((lane >> 3) & 1) * 4;

    {
        int row = tid >> 3, ch = tid & 7;
        cp16(sbase + (uint32_t)(AT_QH + row * 36 + ch * 4) * 4,
             qh + (size_t)(qbase + row) * rst + h * 32 + ch * 4);
        cp16(sbase + (uint32_t)(AT_QL + row * 36 + ch * 4) * 4,
             ql + (size_t)(qbase + row) * rst + h * 32 + ch * 4);
    }
    for (int t = tid; t < 4096; t += 256) {
        int row = t >> 3, ch = t & 7;
        if (row < len) {
            cp16(sbase + (uint32_t)(AT_KH + row * 36 + ch * 4) * 4,
                 kh + (size_t)(b * SS + row) * rst + h * 32 + ch * 4);
            cp16(sbase + (uint32_t)(AT_KL + row * 36 + ch * 4) * 4,
                 kl + (size_t)(b * SS + row) * rst + h * 32 + ch * 4);
        }
    }
    cp_commit(); cp_wait0();
    __syncthreads();

    float acc[2][8][4];
    #pragma unroll
    for (int i = 0; i < 2; i++)
        #pragma unroll
        for (int j = 0; j < 8; j++)
            #pragma unroll
            for (int r = 0; r < 4; r++) acc[i][j][r] = 0.f;

    if (warp * 64 < len) {
        #pragma unroll
        for (int c = 0; c < 4; c++) {
            uint32_t ah[2][4], al[2][4];
            #pragma unroll
            for (int i = 0; i < 2; i++) {
                uint32_t ad = sbase +
                    (uint32_t)(AT_QH + (i * 16 + l15) * 36 + c * 8 + lc4) * 4;
                ldsm4(ah[i], ad);
                ldsm4(al[i], ad + (AT_QL - AT_QH) * 4);
            }
            #pragma unroll
            for (int j = 0; j < 8; j++) {
                uint32_t bd = sbase +
                    (uint32_t)(AT_KH + (warp * 64 + j * 8 + l7) * 36 + c * 8 + lb4) * 4;
                uint32_t bh[2], bl[2];
                ldsm2(bh, bd);
                ldsm2(bl, bd + (AT_KL - AT_KH) * 4);
                #pragma unroll
                for (int i = 0; i < 2; i++) {
                    mma16816(acc[i][j], ah[i], bh);
                    mma16816(acc[i][j], al[i], bh);
                    mma16816(acc[i][j], ah[i], bl);
                }
            }
        }
    }

    const float scale = 0.125f;
    #pragma unroll
    for (int i = 0; i < 2; i++)
        #pragma unroll
        for (int j = 0; j < 8; j++) {
            int c0 = warp * 64 + j * 8 + tig * 2;
            bool m0 = c0 < len, m1 = (c0 + 1) < len;
            acc[i][j][0] = m0 ? acc[i][j][0] * scale : -1e9f;
            acc[i][j][1] = m1 ? acc[i][j][1] * scale : -1e9f;
            acc[i][j][2] = m0 ? acc[i][j][2] * scale : -1e9f;
            acc[i][j][3] = m1 ? acc[i][j][3] * scale : -1e9f;
        }

    float* redM = (float*)(sm + AT_RED);
    float* redS = redM + 256;

    float rmax[2][2];
    #pragma unroll
    for (int i = 0; i < 2; i++)
        #pragma unroll
        for (int sub = 0; sub < 2; sub++) {
            float m = -1e30f;
            #pragma unroll
            for (int j = 0; j < 8; j++) {
                m = fmaxf(m, acc[i][j][2 * sub]);
                m = fmaxf(m, acc[i][j][2 * sub + 1]);
            }
            m = fmaxf(m, __shfl_xor_sync(0xffffffffu, m, 1));
            m = fmaxf(m, __shfl_xor_sync(0xffffffffu, m, 2));
            if (tig == 0) redM[(i * 16 + sub * 8 + g) * 8 + warp] = m;
        }
    __syncthreads();
    #pragma unroll
    for (int i = 0; i < 2; i++)
        #pragma unroll
        for (int sub = 0; sub < 2; sub++) {
            int row = i * 16 + sub * 8 + g;
            float m = -1e30f;
            #pragma unroll
            for (int w = 0; w < 8; w++) m = fmaxf(m, redM[row * 8 + w]);
            rmax[i][sub] = m;
        }

    #pragma unroll
    for (int i = 0; i < 2; i++)
        #pragma unroll
        for (int sub = 0; sub < 2; sub++) {
            float s = 0.f;
            #pragma unroll
            for (int j = 0; j < 8; j++) {
                float e0 = __expf(acc[i][j][2 * sub]     - rmax[i][sub]);
                float e1 = __expf(acc[i][j][2 * sub + 1] - rmax[i][sub]);
                acc[i][j][2 * sub] = e0; acc[i][j][2 * sub + 1] = e1;
                s += e0 + e1;
            }
            s += __shfl_xor_sync(0xffffffffu, s, 1);
            s += __shfl_xor_sync(0xffffffffu, s, 2);
            if (tig == 0) redS[(i * 16 + sub * 8 + g) * 8 + warp] = s;
        }
    __syncthreads();

    #pragma unroll
    for (int i = 0; i < 2; i++)
        #pragma unroll
        for (int sub = 0; sub < 2; sub++) {
            int row = i * 16 + sub * 8 + g;
            float s = 0.f;
            #pragma unroll
            for (int w = 0; w < 8; w++) s += redS[row * 8 + w];
            float inv = 1.f / s;
            #pragma unroll
            for (int j = 0; j < 8; j++) {
                float p0 = acc[i][j][2 * sub] * inv;
                float p1 = acc[i][j][2 * sub + 1] * inv;
                float h0 = __bfloat162float(__float2bfloat16_rn(p0));
                float h1 = __bfloat162float(__float2bfloat16_rn(p1));
                int wi = row * 260 + warp * 32 + j * 4 + tig;
                sm[AT_PH + wi] = pack_bf16(h0, h1);
                sm[AT_PL + wi] = pack_bf16(p0 - h0, p1 - h1);
            }
        }
    __syncthreads();

    // load V (row-major [s][d], same layout as K) over the K region.
    // rows < vrows (= 16*nc): PV tail reads [len, vrows) multiplied by P==0,
    // and gmem there is finite — avoids uninitialized-smem NaN poisoning.
    for (int t = tid; t < 4096; t += 256) {
        int row = t >> 3, ch = t & 7;
        if (row < vrows) {
            cp16(sbase + (uint32_t)(AT_KH + row * 36 + ch * 4) * 4,
                 vh + (size_t)(b * SS + row) * rst + h * 32 + ch * 4);
            cp16(sbase + (uint32_t)(AT_KL + row * 36 + ch * 4) * 4,
                 vl + (size_t)(b * SS + row) * rst + h * 32 + ch * 4);
        }
    }
    cp_commit(); cp_wait0();
    __syncthreads();

    // PV: B fragments via ldmatrix.x2.trans on V[s][d]
    const int wm2 = warp >> 2, wn2 = warp & 3;
    float oacc[2][4];
    #pragma unroll
    for (int j = 0; j < 2; j++)
        #pragma unroll
        for (int r = 0; r < 4; r++) oacc[j][r] = 0.f;

    #pragma unroll 4
    for (int c = 0; c < nc; c++) {
        uint32_t ah[4], al[4];
        uint32_t ad = sbase +
            (uint32_t)(AT_PH + (wm2 * 16 + l15) * 260 + c * 8 + lc4) * 4;
        ldsm4(ah, ad);
        ldsm4(al, ad + (AT_PL - AT_PH) * 4);
        #pragma unroll
        for (int j = 0; j < 2; j++) {
            uint32_t vd = sbase + (uint32_t)(AT_KH + (c * 16 + l15) * 36) * 4
                        + (uint32_t)(wn2 * 16 + j * 8) * 2;
            uint32_t bh[2], bl[2];
            ldsm2t(bh, vd);
            ldsm2t(bl, vd + (AT_KL - AT_KH) * 4);
            mma16816(oacc[j], ah, bh);
            mma16816(oacc[j], al, bh);
            mma16816(oacc[j], ah, bl);
        }
    }

    #pragma unroll
    for (int j = 0; j < 2; j++) {
        int col = h * DHD + wn2 * 16 + j * 8 + tig * 2;
        int r0 = qbase + wm2 * 16 + g;
        int r1 = r0 + 8;
        *(float2*)(O + (size_t)r0 * DD + col) = make_float2(oacc[j][0], oacc[j][1]);
        *(float2*)(O + (size_t)r1 * DD + col) = make_float2(oacc[j][2], oacc[j][3]);
    }
}

// -------------------- fused residual + LayerNorm + split (one-pass) ---------
__global__ __launch_bounds__(192)
void add_ln(const float* __restrict__ x, const float* __restrict__ y,
            const float* __restrict__ g, const float* __restrict__ bt,
            float* __restrict__ out, uint32_t* __restrict__ s_hi,
            uint32_t* __restrict__ s_lo, const int* __restrict__ lens)
{
    const int row = blockIdx.x;
    if ((row & (SS - 1)) >= lens[row >> 9]) return;
    const int tid = threadIdx.x;
    const int c0 = tid * 4;
    float4 xv = *(const float4*)(x + (size_t)row * DD + c0);
    float4 yv = *(const float4*)(y + (size_t)row * DD + c0);
    float v0 = xv.x + yv.x, v1 = xv.y + yv.y, v2 = xv.z + yv.z, v3 = xv.w + yv.w;
    float s  = v0 + v1 + v2 + v3;
    float sq = v0 * v0 + v1 * v1 + v2 * v2 + v3 * v3;
    blockReduceSum2(s, sq);
    float mean = s * (1.0f / DD);
    float var  = sq * (1.0f / DD) - mean * mean;
    float rstd = rsqrtf(var + 1e-5f);
    float d0 = v0 - mean, d1 = v1 - mean, d2 = v2 - mean, d3 = v3 - mean;
    float4 gv = *(const float4*)(g + c0);
    float4 bv = *(const float4*)(bt + c0);
    float o0 = d0 * rstd * gv.x + bv.x;
    float o1 = d1 * rstd * gv.y + bv.y;
    float o2 = d2 * rstd * gv.z + bv.z;
    float o3 = d3 * rstd * gv.w + bv.w;
    *(float4*)(out + (size_t)row * DD + c0) = make_float4(o0, o1, o2, o3);
    float h0 = __bfloat162float(__float2bfloat16_rn(o0));
    float h1 = __bfloat162float(__float2bfloat16_rn(o1));
    float h2 = __bfloat162float(__float2bfloat16_rn(o2));
    float h3 = __bfloat162float(__float2bfloat16_rn(o3));
    size_t w = (size_t)row * (DD / 2) + tid * 2;
    s_hi[w]     = pack_bf16(h0, h1);
    s_lo[w]     = pack_bf16(o0 - h0, o1 - h1);
    s_hi[w + 1] = pack_bf16(h2, h3);
    s_lo[w + 1] = pack_bf16(o2 - h2, o3 - h3);
}

// -------------------- masked mean pool + output projection -------------------
__global__ __launch_bounds__(256)
void pool_out(const float* __restrict__ hbuf, const int* __restrict__ lens,
              const float* __restrict__ ow, const float* __restrict__ ob,
              float* __restrict__ out)
{
    __shared__ float ps[8][DD];
    const int b = blockIdx.x;
    const int tid = threadIdx.x;
    const int warp = tid >> 5, lane = tid & 31;
    const int len = lens[b];
    float r[24];
    #pragma unroll
    for (int i = 0; i < 24; i++) r[i] = 0.f;
    for (int sp = warp; sp < len; sp += 8) {
        const float* row = hbuf + (size_t)(b * SS + sp) * DD;
        #pragma unroll
        for (int i = 0; i < 24; i++) r[i] += row[i * 32 + lane];
    }
    #pragma unroll
    for (int i = 0; i < 24; i++) ps[warp][i * 32 + lane] = r[i];
    __syncthreads();
    const float inv = 1.0f / (float)len;
    float acc = 0.f;
    #pragma unroll
    for (int i = 0; i < 3; i++) {
        int d = tid + i * 256;
        float s = 0.f;
        #pragma unroll
        for (int w = 0; w < 8; w++) s += ps[w][d];
        acc += s * inv * ow[d];
    }
    float tot = blockReduceSum(acc);
    if (tid == 0) out[b] = tot + ob[0];
}

// -------------------- launcher --------------------
extern "C" void kernel_launch(void* const* d_in, const int* in_sizes, int n_in,
                              void* d_out, int out_size)
{
    const float* x    = (const float*)d_in[0];
    const int*   lens = (const int*)  d_in[1];
    const float* in_w = (const float*)d_in[2];
    const float* in_b = (const float*)d_in[3];
    const float* pos  = (const float*)d_in[4];
    const float* qw   = (const float*)d_in[5];
    const float* qb   = (const float*)d_in[6];
    const float* kw   = (const float*)d_in[7];
    const float* kb   = (const float*)d_in[8];
    const float* vw   = (const float*)d_in[9];
    const float* vb   = (const float*)d_in[10];
    const float* w1   = (const float*)d_in[11];
    const float* b1   = (const float*)d_in[12];
    const float* w2   = (const float*)d_in[13];
    const float* b2   = (const float*)d_in[14];
    const float* ln1g = (const float*)d_in[15];
    const float* ln1b = (const float*)d_in[16];
    const float* ln2g = (const float*)d_in[17];
    const float* ln2b = (const float*)d_in[18];
    const float* ow   = (const float*)d_in[19];
    const float* ob   = (const float*)d_in[20];
    float* out = (float*)d_out;

    float *h, *o, *qkvb;
    uint32_t *xs_hi, *xs_lo, *hs_hi, *hs_lo, *ff_hi, *ff_lo, *w_hi, *w_lo;
    uint32_t *qkv_hi, *qkv_lo;
    cudaGetSymbolAddress((void**)&h,  g_h);
    cudaGetSymbolAddress((void**)&o,  g_o);
    cudaGetSymbolAddress((void**)&qkvb, g_qkvb);
    cudaGetSymbolAddress((void**)&xs_hi, g_xs_hi);
    cudaGetSymbolAddress((void**)&xs_lo, g_xs_lo);
    cudaGetSymbolAddress((void**)&hs_hi, g_hs_hi);
    cudaGetSymbolAddress((void**)&hs_lo, g_hs_lo);
    cudaGetSymbolAddress((void**)&ff_hi, g_ff_hi);
    cudaGetSymbolAddress((void**)&ff_lo, g_ff_lo);
    cudaGetSymbolAddress((void**)&qkv_hi, g_qkv_hi);
    cudaGetSymbolAddress((void**)&qkv_lo, g_qkv_lo);
    cudaGetSymbolAddress((void**)&w_hi,  g_w_hi);
    cudaGetSymbolAddress((void**)&w_lo,  g_w_lo);

    cudaFuncSetAttribute(gemm_tc, cudaFuncAttributeMaxDynamicSharedMemorySize,
                         GEMM_SMEM);
    cudaFuncSetAttribute(gemm_big, cudaFuncAttributeMaxDynamicSharedMemorySize,
                         GB_SMEM);
    cudaFuncSetAttribute(attn_tc, cudaFuncAttributeMaxDynamicSharedMemorySize,
                         ATTN_SMEM);

    const long QKV_L = 3L * DD * DD / 2;
    const long FFN_L = (long)DD * DFF_ / 2;

    const dim3 gD(DD / 128, MROWS / 128);
    const dim3 gQKV(3 * DD / 128, MROWS / 128);
    const dim3 gF(DFF_ / 128, MROWS / 128);
    const dim3 gA(SS / 32, HH, BB);

    xsplit<<<(MROWS * INF_ / 2 + 255) / 256, 256>>>(x, xs_hi, xs_lo, MROWS * INF_ / 2);
    wsplit<<<dim3(DD/64, 1, 1), 256>>>(in_w, w_hi + W_INW, w_lo + W_INW,
                                       INF_, DD, 12288);
    gemm_tc<<<gD, 256, GEMM_SMEM>>>(xs_hi, xs_lo, w_hi + W_INW, w_lo + W_INW,
                                    in_b, pos, h, hs_hi, hs_lo, DD, INF_, 0, lens);
    catb<<<(LL * 3 * DD + 255) / 256, 256>>>(qb, kb, vb, qkvb);
    wsplit3<<<dim3(DD/64, DD/64, 3*LL), 256>>>(qw, kw, vw, w_hi + W_QKV, w_lo + W_QKV);

    for (int l = 0; l < LL; l++) {
        const size_t woQ = (size_t)l * QKV_L;
        const size_t woF = (size_t)l * FFN_L;
        const size_t bo  = (size_t)l * DD;
        gemm_big<<<gQKV, 256, GB_SMEM>>>(hs_hi, hs_lo,
                                         w_hi + W_QKV + woQ, w_lo + W_QKV + woQ,
                                         qkvb + (size_t)l * 3 * DD, nullptr,
                                         qkv_hi, qkv_lo, 3 * DD, DD, 0, lens);
        if (l == 0) {
            wsplit<<<dim3(DFF_/64, DD/64, LL), 256>>>(w1, w_hi + W_W1, w_lo + W_W1,
                                                      DD, DFF_, FFN_L);
            wsplit<<<dim3(DD/64, DFF_/64, LL), 256>>>(w2, w_hi + W_W2, w_lo + W_W2,
                                                      DFF_, DD, FFN_L);
        }
        attn_tc<<<gA, 256, ATTN_SMEM>>>(qkv_hi, qkv_lo,
                                        qkv_hi + (DD / 2), qkv_lo + (DD / 2),
                                        qkv_hi + 2 * (DD / 2), qkv_lo + 2 * (DD / 2),
                                        lens, o, 3 * DD / 2);
        add_ln<<<MROWS, 192>>>(h, o, ln1g + bo, ln1b + bo, h, hs_hi, hs_lo, lens);
        gemm_big<<<gF, 256, GB_SMEM>>>(hs_hi, hs_lo,
                                       w_hi + W_W1 + woF, w_lo + W_W1 + woF,
                                       b1 + (size_t)l * DFF_, nullptr,
                                       ff_hi, ff_lo, DFF_, DD, 1, lens);
        gemm_big<<<gD, 256, GB_SMEM>>>(ff_hi, ff_lo,
                                       w_hi + W_W2 + woF, w_lo + W_W2 + woF,
                                       b2 + bo, o, nullptr, nullptr, DD, DFF_, 0, lens);
        add_ln<<<MROWS, 192>>>(h, o, ln2g + bo, ln2b + bo, h, hs_hi, hs_lo, lens);
    }

    pool_out<<<BB, 256>>>(h, lens, ow, ob, out);
}